// round 5
// baseline (speedup 1.0000x reference)
#include <cuda_runtime.h>
#include <math.h>

// Problem constants
constexpr int NB  = 8;
constexpr int NT  = 2048;
constexpr int ND  = 1024;
constexpr int NP  = 512;
constexpr int NS  = 256;
constexpr int NH  = 256;
constexpr int NBT = NB * NT;      // 16384

constexpr float TAUF = 1e-5f;     // at-risk flag window (fp32 pass error ~1e-6)

// ---------------- device scratch (static allocations only) ----------------
__device__ float g_h[NBT * NH];          // tokens@w1 (pre-relu)
__device__ float g_q[NBT * NS];          // tokens@wq
__device__ float g_scores[NBT];
__device__ int   g_order[NBT];           // per-batch sorted token indices
__device__ float g_sscores[NBT];         // per-batch sorted scores
__device__ float g_st[NB * NP * ND];     // top-512 sorted tokens
__device__ float g_sum[NB * NP * NS];    // summaries
__device__ float g_pool[NB * NP * NS];   // updated pool
__device__ float g_pri[NB * NP];
__device__ int   g_counts[NB];
__device__ float g_k[NB * NP * NS];      // pool@wk
__device__ float g_kT[NB * NS * NP];     // transposed k
__device__ float g_v[NB * NP * ND];      // pool@wv
__device__ float g_attn[NB * NT * NP];   // attention weights
__device__ int           g_flagcnt;
__device__ int           g_flaglist[NBT];
__device__ unsigned char g_flag[NBT];

// ------- 128x128x8 double-buffered SGEMM, 8x8 microtile, 256 threads -------
__global__ __launch_bounds__(256, 2)
void sgemm128_kernel(const float* __restrict__ A, const float* __restrict__ Bm,
                     float* __restrict__ C, int M, int N, int K,
                     long long sA, long long sB, long long sC) {
    A  += (long long)blockIdx.z * sA;
    Bm += (long long)blockIdx.z * sB;
    C  += (long long)blockIdx.z * sC;
    __shared__ float As[2][8][128];    // k-major (transposed on store)
    __shared__ float Bs[2][8][128];

    const int tid  = threadIdx.x;
    const int row0 = blockIdx.y * 128, col0 = blockIdx.x * 128;
    const int ar = tid >> 1;              // 0..127
    const int ac = (tid & 1) << 2;        // 0 or 4
    const int br = tid >> 5;              // 0..7
    const int bc = (tid & 31) << 2;       // 0..124
    const float* Ap = A + (long long)(row0 + ar) * K + ac;
    const float* Bp = Bm + (long long)br * N + col0 + bc;
    const int tx = (tid & 15) << 3;
    const int ty = (tid >> 4) << 3;

    float acc[8][8] = {};
    float4 av = *(const float4*)Ap;
    float4 bv = *(const float4*)Bp;
    int buf = 0;
    As[0][ac + 0][ar] = av.x;
    As[0][ac + 1][ar] = av.y;
    As[0][ac + 2][ar] = av.z;
    As[0][ac + 3][ar] = av.w;
    *(float4*)&Bs[0][br][bc] = bv;
    __syncthreads();

    for (int k0 = 8; k0 <= K; k0 += 8) {
        if (k0 < K) {
            av = *(const float4*)(Ap + k0);
            bv = *(const float4*)(Bp + (long long)k0 * N);
        }
#pragma unroll
        for (int kk = 0; kk < 8; kk++) {
            float a[8], b[8];
            *(float4*)&a[0] = *(const float4*)&As[buf][kk][ty];
            *(float4*)&a[4] = *(const float4*)&As[buf][kk][ty + 4];
            *(float4*)&b[0] = *(const float4*)&Bs[buf][kk][tx];
            *(float4*)&b[4] = *(const float4*)&Bs[buf][kk][tx + 4];
#pragma unroll
            for (int i = 0; i < 8; i++)
#pragma unroll
                for (int j = 0; j < 8; j++)
                    acc[i][j] = fmaf(a[i], b[j], acc[i][j]);
        }
        if (k0 < K) {
            buf ^= 1;
            As[buf][ac + 0][ar] = av.x;
            As[buf][ac + 1][ar] = av.y;
            As[buf][ac + 2][ar] = av.z;
            As[buf][ac + 3][ar] = av.w;
            *(float4*)&Bs[buf][br][bc] = bv;
            __syncthreads();
        }
    }
#pragma unroll
    for (int i = 0; i < 8; i++) {
        float* crow = C + (long long)(row0 + ty + i) * N + col0 + tx;
        *(float4*)crow       = make_float4(acc[i][0], acc[i][1], acc[i][2], acc[i][3]);
        *(float4*)(crow + 4) = make_float4(acc[i][4], acc[i][5], acc[i][6], acc[i][7]);
    }
}

// ---------------- scores: sigmoid(relu(h) . w2), one warp per row ----------
__global__ void score_kernel(const float* __restrict__ w2) {
    int gw = (blockIdx.x * blockDim.x + threadIdx.x) >> 5;
    int lane = threadIdx.x & 31;
    if (gw >= NBT) return;
    const float* hr = g_h + (long long)gw * NH;
    float s = 0.f;
#pragma unroll
    for (int j = 0; j < NH / 32; j++) {
        int c = lane + (j << 5);
        float v = hr[c];
        v = fmaxf(v, 0.f);
        s = fmaf(v, w2[c], s);
    }
#pragma unroll
    for (int o = 16; o; o >>= 1) s += __shfl_xor_sync(0xffffffffu, s, o);
    if (lane == 0) g_scores[gw] = 1.0f / (1.0f + expf(-s));
}

// ---------------- per-batch bitonic sort, descending score / ascending idx --
__global__ void sort_kernel() {
    __shared__ float sk[NT];
    __shared__ int   si[NT];
    int b = blockIdx.x, t = threadIdx.x;   // 1024 threads
    sk[t]        = g_scores[b * NT + t];        si[t]        = t;
    sk[t + 1024] = g_scores[b * NT + t + 1024]; si[t + 1024] = t + 1024;
    __syncthreads();
    for (int kk = 2; kk <= NT; kk <<= 1) {
        for (int j = kk >> 1; j > 0; j >>= 1) {
            for (int i = t; i < NT; i += 1024) {
                int ixj = i ^ j;
                if (ixj > i) {
                    bool ord = ((i & kk) == 0);
                    float s1 = sk[i], s2 = sk[ixj];
                    int   i1 = si[i], i2 = si[ixj];
                    bool pre = (s2 > s1) || (s2 == s1 && i2 < i1);
                    if (pre == ord) { sk[i] = s2; sk[ixj] = s1; si[i] = i2; si[ixj] = i1; }
                }
            }
            __syncthreads();
        }
    }
    g_order[b * NT + t]          = si[t];
    g_order[b * NT + t + 1024]   = si[t + 1024];
    g_sscores[b * NT + t]        = sk[t];
    g_sscores[b * NT + t + 1024] = sk[t + 1024];
}

// ---------------- at-risk flagging ----------------
__global__ void reset_flags_kernel() {
    int i = blockIdx.x * blockDim.x + threadIdx.x;
    if (i < NBT) g_flag[i] = 0;
    if (i == 0) g_flagcnt = 0;
}

__global__ void flag_ab_kernel() {
    int i = blockIdx.x * blockDim.x + threadIdx.x;   // global sorted position
    if (i >= NBT) return;
    int b = i >> 11, p = i & (NT - 1);
    float s = g_sscores[i];
    if (fabsf(s - 0.5f) < TAUF) g_flag[b * NT + g_order[i]] = 1;
    if (p + 1 < NT) {
        float s2 = g_sscores[i + 1];
        if (fabsf(s - s2) < TAUF) {
            g_flag[b * NT + g_order[i]] = 1;
            g_flag[b * NT + g_order[i + 1]] = 1;
        }
    }
}

__global__ void flag_c_kernel(const float* __restrict__ pri_in) {
    __shared__ float pr[NP];
    int b = blockIdx.y;
    for (int i = threadIdx.x; i < NP; i += blockDim.x) pr[i] = pri_in[b * NP + i];
    __syncthreads();
    int t = blockIdx.x * blockDim.x + threadIdx.x;
    if (t >= NT) return;
    float s = g_scores[b * NT + t];
    bool hit = false;
#pragma unroll 8
    for (int i = 0; i < NP; i++) hit |= (fabsf(s - pr[i]) < TAUF);
    if (hit) g_flag[b * NT + t] = 1;
}

__global__ void compact_kernel() {
    int i = blockIdx.x * blockDim.x + threadIdx.x;
    if (i < NBT && g_flag[i]) {
        int pos = atomicAdd(&g_flagcnt, 1);
        g_flaglist[pos] = i;
    }
}

// ---- double-float helpers (compensated fp32; error ~ n*eps^2 ~ 4e-12) ----
__device__ __forceinline__ void twoProd(float a, float b, float& p, float& e) {
    p = a * b;
    e = fmaf(a, b, -p);
}
__device__ __forceinline__ void twoSum(float a, float b, float& s, float& e) {
    s = a + b;
    float bb = s - a;
    e = (a - (s - bb)) + (b - bb);
}

// high-precision recompute of flagged tokens' scores via compensated fp32
__global__ void recompute_kernel(const float* __restrict__ tokens,
                                 const float* __restrict__ w1,
                                 const float* __restrict__ w2) {
    __shared__ double red[256];
    int j = threadIdx.x;   // 256 threads = H columns
    int n = g_flagcnt;
    if (blockIdx.x >= n) return;
    for (int li = blockIdx.x; li < n; li += gridDim.x) {
        int g = g_flaglist[li];
        const float* x = tokens + (long long)g * ND;
        const float* wcol = w1 + j;
        float hi = 0.f, lo = 0.f;
        for (int d = 0; d < ND; d++) {
            float p, pe, t;
            twoProd(x[d], wcol[(long long)d * NH], p, pe);
            twoSum(hi, p, hi, t);
            lo += t + pe;
        }
        double hd = (double)hi + (double)lo;
        float hf = fmaxf((float)hd, 0.0f);        // round to fp32, relu
        red[j] = (double)hf * (double)w2[j];
        __syncthreads();
        for (int s = 128; s; s >>= 1) {
            if (j < s) red[j] += red[j + s];
            __syncthreads();
        }
        if (j == 0) {
            double z = red[0];
            g_scores[g] = (float)(1.0 / (1.0 + exp(-z)));
        }
        __syncthreads();
    }
}

// ---------------- gather top-512 sorted tokens ----------------
__global__ void gather_kernel(const float* __restrict__ tokens) {
    int b = blockIdx.y, slot = blockIdx.x;
    int src = g_order[b * NT + slot];
    const float4* s4 = (const float4*)(tokens + ((long long)b * NT + src) * ND);
    float4* d4 = (float4*)(g_st + ((long long)b * NP + slot) * ND);
    d4[threadIdx.x] = s4[threadIdx.x];
}

// ---------------- wide pool copy (input pool -> working pool) --------------
__global__ void copy_pool_kernel(const float* __restrict__ pool_in) {
    int i = blockIdx.x * blockDim.x + threadIdx.x;   // float4 index
    ((float4*)g_pool)[i] = ((const float4*)pool_in)[i];
}

// ------- sequential pool update: 1 warp per batch, no block syncs ----------
__global__ void update_kernel(const float* __restrict__ pri_in,
                              const int* __restrict__ counts_in) {
    int b = blockIdx.x;
    int lane = threadIdx.x;    // 32 threads
    __shared__ float pri[NP];
#pragma unroll
    for (int j = 0; j < NP / 32; j++) pri[lane + (j << 5)] = pri_in[b * NP + lane + (j << 5)];
    int cnt = counts_in[b];    // uniform across warp
    __syncwarp();

    float*       poolb = g_pool + (long long)b * NP * NS;
    const float* summb = g_sum + (long long)b * NP * NS;
    const float* ss    = g_sscores + b * NT;

    for (int slot = 0; slot < NP; slot++) {
        float sc = ss[slot];
        if (!(sc > 0.5f)) continue;            // uniform branch
        if (cnt < NP) {                        // insert phase
#pragma unroll
            for (int j = 0; j < NS / 32; j++)
                poolb[cnt * NS + lane + (j << 5)] = summb[slot * NS + lane + (j << 5)];
            if (lane == 0) pri[cnt] = sc;
            cnt++;
            __syncwarp();
        }
        if (cnt >= NP) {                       // replace-min (post-insert count)
            float best = 1e30f; int bidx = 0;
#pragma unroll
            for (int j = 0; j < NP / 32; j++) {
                int idx = lane + (j << 5);     // ascending per lane -> first-min kept
                float v = pri[idx];
                if (v < best) { best = v; bidx = idx; }
            }
#pragma unroll
            for (int o = 16; o; o >>= 1) {
                float ov = __shfl_xor_sync(0xffffffffu, best, o);
                int   oi = __shfl_xor_sync(0xffffffffu, bidx, o);
                if (ov < best || (ov == best && oi < bidx)) { best = ov; bidx = oi; }
            }
            if (sc > best) {
#pragma unroll
                for (int j = 0; j < NS / 32; j++)
                    poolb[bidx * NS + lane + (j << 5)] = summb[slot * NS + lane + (j << 5)];
                if (lane == 0) pri[bidx] = sc;
                __syncwarp();
            }
        }
    }
    __syncwarp();
#pragma unroll
    for (int j = 0; j < NP / 32; j++) g_pri[b * NP + lane + (j << 5)] = pri[lane + (j << 5)];
    if (lane == 0) g_counts[b] = cnt;
}

// ---------------- transpose k[b,P,S] -> kT[b,S,P] ----------------
__global__ void transpose_kernel() {
    __shared__ float tile[32][33];
    int b = blockIdx.z;
    int p0 = blockIdx.x * 32, s0 = blockIdx.y * 32;
    const float* src = g_k + (long long)b * NP * NS;
    float* dst = g_kT + (long long)b * NS * NP;
    int x = threadIdx.x, y = threadIdx.y;
#pragma unroll
    for (int i = 0; i < 32; i += 8)
        tile[y + i][x] = src[(p0 + y + i) * NS + s0 + x];
    __syncthreads();
#pragma unroll
    for (int i = 0; i < 32; i += 8)
        dst[(s0 + y + i) * NP + p0 + x] = tile[x][y + i];
}

// ---------------- masked softmax over attn rows (warp per row) -------------
__global__ void softmax_kernel() {
    int gw = (blockIdx.x * blockDim.x + threadIdx.x) >> 5;
    int lane = threadIdx.x & 31;
    if (gw >= NBT) return;
    int b = gw >> 11;
    int cnt = g_counts[b];
    float* row = g_attn + (long long)gw * NP;
    float vals[NP / 32];
    float m = -1e30f;
#pragma unroll
    for (int j = 0; j < NP / 32; j++) {
        int p = lane + (j << 5);
        float v = row[p] * 0.0625f;   // 1/sqrt(256)
        vals[j] = v;
        if (p < cnt) m = fmaxf(m, v);
    }
#pragma unroll
    for (int o = 16; o; o >>= 1) m = fmaxf(m, __shfl_xor_sync(0xffffffffu, m, o));
    float s = 0.f;
#pragma unroll
    for (int j = 0; j < NP / 32; j++) {
        int p = lane + (j << 5);
        float e = (p < cnt) ? expf(vals[j] - m) : 0.f;
        vals[j] = e;
        s += e;
    }
#pragma unroll
    for (int o = 16; o; o >>= 1) s += __shfl_xor_sync(0xffffffffu, s, o);
    float inv = (cnt > 0) ? 1.f / s : 0.f;
#pragma unroll
    for (int j = 0; j < NP / 32; j++) row[lane + (j << 5)] = vals[j] * inv;
}

// ---------------- export pool / priorities / counts into d_out -------------
__global__ void export_kernel(float* __restrict__ dst) {
    int i = blockIdx.x * blockDim.x + threadIdx.x;
    constexpr int PS = NB * NP * NS;
    if (i < PS) dst[i] = g_pool[i];
    else if (i < PS + NB * NP) dst[i] = g_pri[i - PS];
    else if (i < PS + NB * NP + NB) dst[i] = (float)g_counts[i - PS - NB * NP];
}

// ---------------- launch ----------------
extern "C" void kernel_launch(void* const* d_in, const int* in_sizes, int n_in,
                              void* d_out, int out_size) {
    const float* tokens = (const float*)d_in[0];
    const float* pool   = (const float*)d_in[1];
    const float* pri    = (const float*)d_in[2];
    const int*   counts = (const int*)d_in[3];
    const float* w1     = (const float*)d_in[4];
    const float* w2     = (const float*)d_in[5];
    const float* w_sum  = (const float*)d_in[6];
    const float* wq     = (const float*)d_in[7];
    const float* wk     = (const float*)d_in[8];
    const float* wv     = (const float*)d_in[9];
    float* out = (float*)d_out;
    (void)in_sizes; (void)n_in;

    float *ph, *pq, *pst, *psum, *ppool, *pk, *pkT, *pv, *pattn;
    cudaGetSymbolAddress((void**)&ph,    g_h);
    cudaGetSymbolAddress((void**)&pq,    g_q);
    cudaGetSymbolAddress((void**)&pst,   g_st);
    cudaGetSymbolAddress((void**)&psum,  g_sum);
    cudaGetSymbolAddress((void**)&ppool, g_pool);
    cudaGetSymbolAddress((void**)&pk,    g_k);
    cudaGetSymbolAddress((void**)&pkT,   g_kT);
    cudaGetSymbolAddress((void**)&pv,    g_v);
    cudaGetSymbolAddress((void**)&pattn, g_attn);

    // 1. h = tokens @ w1
    sgemm128_kernel<<<dim3(NH / 128, NBT / 128, 1), 256>>>(tokens, w1, ph, NBT, NH, ND, 0, 0, 0);
    // 2. q = tokens @ wq
    sgemm128_kernel<<<dim3(NS / 128, NBT / 128, 1), 256>>>(tokens, wq, pq, NBT, NS, ND, 0, 0, 0);
    // 3. scores (fp32 fast pass)
    score_kernel<<<NBT / 8, 256>>>(w2);
    // 4. provisional sort
    sort_kernel<<<NB, 1024>>>();
    // 5. flag at-risk tokens and recompute them precisely (df64)
    reset_flags_kernel<<<NBT / 256, 256>>>();
    flag_ab_kernel<<<NBT / 256, 256>>>();
    flag_c_kernel<<<dim3(NT / 256, NB), 256>>>(pri);
    compact_kernel<<<NBT / 256, 256>>>();
    recompute_kernel<<<512, 256>>>(tokens, w1, w2);
    // 6. final sort with corrected scores
    sort_kernel<<<NB, 1024>>>();
    // 7. gather top-512 tokens
    gather_kernel<<<dim3(NP, NB), 256>>>(tokens);
    // 8. summaries = sorted_tokens @ w_sum
    sgemm128_kernel<<<dim3(NS / 128, NB * NP / 128, 1), 256>>>(pst, w_sum, psum, NB * NP, NS, ND, 0, 0, 0);
    // 9. pool copy (wide) + sequential per-batch update (1 warp per batch)
    copy_pool_kernel<<<(NB * NP * NS / 4) / 256, 256>>>(pool);
    update_kernel<<<NB, 32>>>(pri, counts);
    // 10. k = pool @ wk
    sgemm128_kernel<<<dim3(NS / 128, NB * NP / 128, 1), 256>>>(ppool, wk, pk, NB * NP, NS, NS, 0, 0, 0);
    // 11. transpose k -> kT
    transpose_kernel<<<dim3(NP / 32, NS / 32, NB), dim3(32, 8)>>>();
    // 12. v = pool @ wv
    sgemm128_kernel<<<dim3(ND / 128, NB * NP / 128, 1), 256>>>(ppool, wv, pv, NB * NP, ND, NS, 0, 0, 0);
    // 13. attn = q @ kT  (batched)
    sgemm128_kernel<<<dim3(NP / 128, NT / 128, NB), 256>>>(pq, pkT, pattn, NT, NP, NS,
        (long long)NT * NS, (long long)NS * NP, (long long)NT * NP);
    // 14. masked softmax
    softmax_kernel<<<NBT / 8, 256>>>();
    // 15. retrieved = attn @ v  (batched) -> d_out
    sgemm128_kernel<<<dim3(ND / 128, NT / 128, NB), 256>>>(pattn, pv, out, NT, ND, NP,
        (long long)NT * NP, (long long)NP * ND, (long long)NT * ND);
    // 16. export pool / priorities / counts
    constexpr int RET = NBT * ND;
    constexpr int REST = NB * NP * NS + NB * NP + NB;
    if (out_size >= RET + REST)
        export_kernel<<<(REST + 255) / 256, 256>>>(out + (long long)RET);
}

// round 6
// speedup vs baseline: 1.3462x; 1.3462x over previous
#include <cuda_runtime.h>
#include <math.h>

// Problem constants
constexpr int NB  = 8;
constexpr int NT  = 2048;
constexpr int ND  = 1024;
constexpr int NP  = 512;
constexpr int NS  = 256;
constexpr int NH  = 256;
constexpr int NBT = NB * NT;      // 16384

constexpr float TAUF = 1e-5f;     // at-risk flag window (fp32 pass error ~1e-6)

// ---------------- device scratch (static allocations only) ----------------
__device__ float g_h[NBT * NH];          // tokens@w1 (pre-relu)
__device__ float g_q[NBT * NS];          // qk = tokens@(wq@wk^T)
__device__ float g_scores[NBT];
__device__ int   g_order[NBT];           // per-batch sorted token indices
__device__ float g_sscores[NBT];         // per-batch sorted scores
__device__ float g_st[NB * NP * ND];     // top-512 sorted tokens
__device__ float g_sum[NB * NP * NS];    // summaries
__device__ float g_pool[NB * NP * NS];   // updated pool
__device__ float g_pri[NB * NP];
__device__ int   g_counts[NB];
__device__ float g_wkT[NS * NS];         // wk^T
__device__ float g_wqk[ND * NS];         // wq @ wk^T
__device__ float g_poolT[NB * NS * NP];  // transposed pool
__device__ float g_ap[NBT * NS];         // attn @ pool
__device__ float g_attn[NB * NT * NP];   // attention weights
__device__ int           g_flagcnt;
__device__ int           g_flaglist[NBT];
__device__ unsigned char g_flag[NBT];

// ------- 128x128x8 double-buffered SGEMM, 8x8 microtile, 256 threads -------
__global__ __launch_bounds__(256, 2)
void sgemm128_kernel(const float* __restrict__ A, const float* __restrict__ Bm,
                     float* __restrict__ C, int M, int N, int K,
                     long long sA, long long sB, long long sC) {
    A  += (long long)blockIdx.z * sA;
    Bm += (long long)blockIdx.z * sB;
    C  += (long long)blockIdx.z * sC;
    __shared__ float As[2][8][128];    // k-major (transposed on store)
    __shared__ float Bs[2][8][128];

    const int tid  = threadIdx.x;
    const int row0 = blockIdx.y * 128, col0 = blockIdx.x * 128;
    const int ar = tid >> 1;              // 0..127
    const int ac = (tid & 1) << 2;        // 0 or 4
    const int br = tid >> 5;              // 0..7
    const int bc = (tid & 31) << 2;       // 0..124
    const float* Ap = A + (long long)(row0 + ar) * K + ac;
    const float* Bp = Bm + (long long)br * N + col0 + bc;
    const int tx = (tid & 15) << 3;
    const int ty = (tid >> 4) << 3;

    float acc[8][8] = {};
    float4 av = *(const float4*)Ap;
    float4 bv = *(const float4*)Bp;
    int buf = 0;
    As[0][ac + 0][ar] = av.x;
    As[0][ac + 1][ar] = av.y;
    As[0][ac + 2][ar] = av.z;
    As[0][ac + 3][ar] = av.w;
    *(float4*)&Bs[0][br][bc] = bv;
    __syncthreads();

    for (int k0 = 8; k0 <= K; k0 += 8) {
        if (k0 < K) {
            av = *(const float4*)(Ap + k0);
            bv = *(const float4*)(Bp + (long long)k0 * N);
        }
#pragma unroll
        for (int kk = 0; kk < 8; kk++) {
            float a[8], b[8];
            *(float4*)&a[0] = *(const float4*)&As[buf][kk][ty];
            *(float4*)&a[4] = *(const float4*)&As[buf][kk][ty + 4];
            *(float4*)&b[0] = *(const float4*)&Bs[buf][kk][tx];
            *(float4*)&b[4] = *(const float4*)&Bs[buf][kk][tx + 4];
#pragma unroll
            for (int i = 0; i < 8; i++)
#pragma unroll
                for (int j = 0; j < 8; j++)
                    acc[i][j] = fmaf(a[i], b[j], acc[i][j]);
        }
        if (k0 < K) {
            buf ^= 1;
            As[buf][ac + 0][ar] = av.x;
            As[buf][ac + 1][ar] = av.y;
            As[buf][ac + 2][ar] = av.z;
            As[buf][ac + 3][ar] = av.w;
            *(float4*)&Bs[buf][br][bc] = bv;
            __syncthreads();
        }
    }
#pragma unroll
    for (int i = 0; i < 8; i++) {
        float* crow = C + (long long)(row0 + ty + i) * N + col0 + tx;
        *(float4*)crow       = make_float4(acc[i][0], acc[i][1], acc[i][2], acc[i][3]);
        *(float4*)(crow + 4) = make_float4(acc[i][4], acc[i][5], acc[i][6], acc[i][7]);
    }
}

// ---------------- scores: sigmoid(relu(h) . w2), one warp per row ----------
__global__ void score_kernel(const float* __restrict__ w2) {
    int gw = (blockIdx.x * blockDim.x + threadIdx.x) >> 5;
    int lane = threadIdx.x & 31;
    if (gw >= NBT) return;
    const float* hr = g_h + (long long)gw * NH;
    float s = 0.f;
#pragma unroll
    for (int j = 0; j < NH / 32; j++) {
        int c = lane + (j << 5);
        float v = hr[c];
        v = fmaxf(v, 0.f);
        s = fmaf(v, w2[c], s);
    }
#pragma unroll
    for (int o = 16; o; o >>= 1) s += __shfl_xor_sync(0xffffffffu, s, o);
    if (lane == 0) g_scores[gw] = 1.0f / (1.0f + expf(-s));
}

// ---------------- per-batch bitonic sort, descending score / ascending idx --
__global__ void sort_kernel() {
    __shared__ float sk[NT];
    __shared__ int   si[NT];
    int b = blockIdx.x, t = threadIdx.x;   // 1024 threads
    sk[t]        = g_scores[b * NT + t];        si[t]        = t;
    sk[t + 1024] = g_scores[b * NT + t + 1024]; si[t + 1024] = t + 1024;
    __syncthreads();
    for (int kk = 2; kk <= NT; kk <<= 1) {
        for (int j = kk >> 1; j > 0; j >>= 1) {
            for (int i = t; i < NT; i += 1024) {
                int ixj = i ^ j;
                if (ixj > i) {
                    bool ord = ((i & kk) == 0);
                    float s1 = sk[i], s2 = sk[ixj];
                    int   i1 = si[i], i2 = si[ixj];
                    bool pre = (s2 > s1) || (s2 == s1 && i2 < i1);
                    if (pre == ord) { sk[i] = s2; sk[ixj] = s1; si[i] = i2; si[ixj] = i1; }
                }
            }
            __syncthreads();
        }
    }
    g_order[b * NT + t]          = si[t];
    g_order[b * NT + t + 1024]   = si[t + 1024];
    g_sscores[b * NT + t]        = sk[t];
    g_sscores[b * NT + t + 1024] = sk[t + 1024];
}

// ---------------- at-risk flagging ----------------
__global__ void reset_flags_kernel() {
    int i = blockIdx.x * blockDim.x + threadIdx.x;
    if (i < NBT) g_flag[i] = 0;
    if (i == 0) g_flagcnt = 0;
}

__global__ void flag_ab_kernel() {
    int i = blockIdx.x * blockDim.x + threadIdx.x;   // global sorted position
    if (i >= NBT) return;
    int b = i >> 11, p = i & (NT - 1);
    float s = g_sscores[i];
    if (fabsf(s - 0.5f) < TAUF) g_flag[b * NT + g_order[i]] = 1;
    if (p + 1 < NT) {
        float s2 = g_sscores[i + 1];
        if (fabsf(s - s2) < TAUF) {
            g_flag[b * NT + g_order[i]] = 1;
            g_flag[b * NT + g_order[i + 1]] = 1;
        }
    }
}

__global__ void flag_c_kernel(const float* __restrict__ pri_in) {
    __shared__ float pr[NP];
    int b = blockIdx.y;
    for (int i = threadIdx.x; i < NP; i += blockDim.x) pr[i] = pri_in[b * NP + i];
    __syncthreads();
    int t = blockIdx.x * blockDim.x + threadIdx.x;
    if (t >= NT) return;
    float s = g_scores[b * NT + t];
    bool hit = false;
#pragma unroll 8
    for (int i = 0; i < NP; i++) hit |= (fabsf(s - pr[i]) < TAUF);
    if (hit) g_flag[b * NT + t] = 1;
}

__global__ void compact_kernel() {
    int i = blockIdx.x * blockDim.x + threadIdx.x;
    if (i < NBT && g_flag[i]) {
        int pos = atomicAdd(&g_flagcnt, 1);
        g_flaglist[pos] = i;
    }
}

// exact fp64 recompute of flagged tokens' scores, 4 independent accumulators
__global__ void recompute_kernel(const float* __restrict__ tokens,
                                 const float* __restrict__ w1,
                                 const float* __restrict__ w2) {
    __shared__ double red[256];
    int j = threadIdx.x;   // 256 threads = H columns
    int n = g_flagcnt;
    if (blockIdx.x >= n) return;
    for (int li = blockIdx.x; li < n; li += gridDim.x) {
        int g = g_flaglist[li];
        const float* x = tokens + (long long)g * ND;
        const float* wcol = w1 + j;
        double a0 = 0.0, a1 = 0.0, a2 = 0.0, a3 = 0.0;
        for (int d = 0; d < ND; d += 4) {
            a0 += (double)x[d + 0] * (double)wcol[(long long)(d + 0) * NH];
            a1 += (double)x[d + 1] * (double)wcol[(long long)(d + 1) * NH];
            a2 += (double)x[d + 2] * (double)wcol[(long long)(d + 2) * NH];
            a3 += (double)x[d + 3] * (double)wcol[(long long)(d + 3) * NH];
        }
        double acc = (a0 + a1) + (a2 + a3);
        float hf = fmaxf((float)acc, 0.0f);      // round to fp32, relu
        red[j] = (double)hf * (double)w2[j];
        __syncthreads();
        for (int s = 128; s; s >>= 1) {
            if (j < s) red[j] += red[j + s];
            __syncthreads();
        }
        if (j == 0) {
            double z = red[0];
            g_scores[g] = (float)(1.0 / (1.0 + exp(-z)));
        }
        __syncthreads();
    }
}

// ---------------- gather top-512 sorted tokens ----------------
__global__ void gather_kernel(const float* __restrict__ tokens) {
    int b = blockIdx.y, slot = blockIdx.x;
    int src = g_order[b * NT + slot];
    const float4* s4 = (const float4*)(tokens + ((long long)b * NT + src) * ND);
    float4* d4 = (float4*)(g_st + ((long long)b * NP + slot) * ND);
    d4[threadIdx.x] = s4[threadIdx.x];
}

// ------ sequential pool update (R4 known-good: 256 threads per batch) ------
__global__ void update_kernel(const float* __restrict__ pool_in,
                              const float* __restrict__ pri_in,
                              const int* __restrict__ counts_in) {
    int b = blockIdx.x, t = threadIdx.x;   // 256 threads
    __shared__ float pri[NP];
    __shared__ int   sh_cnt;
    __shared__ float sh_minp;
    __shared__ int   sh_mini;
    const float4* pin  = (const float4*)(pool_in + (long long)b * NP * NS);
    float4*       pout = (float4*)(g_pool + (long long)b * NP * NS);
    for (int i = t; i < NP * NS / 4; i += 256) pout[i] = pin[i];
    pri[t]       = pri_in[b * NP + t];
    pri[t + 256] = pri_in[b * NP + t + 256];
    if (t == 0) sh_cnt = counts_in[b];
    __syncthreads();

    float*       poolb = g_pool + (long long)b * NP * NS;
    const float* summb = g_sum + (long long)b * NP * NS;
    const float* ss    = g_sscores + b * NT;

    for (int slot = 0; slot < NP; slot++) {
        float sc = ss[slot];
        bool has = sc > 0.5f;
        int cnt = sh_cnt;
        if (has && cnt < NP) {                // insert phase
            poolb[cnt * NS + t] = summb[slot * NS + t];
            __syncthreads();
            if (t == 0) { pri[cnt] = sc; sh_cnt = cnt + 1; }
        }
        __syncthreads();
        if (has && sh_cnt >= NP) {            // replace-min (post-insert count)
            if (t < 32) {
                float best = 1e30f; int bidx = 0;
#pragma unroll
                for (int jj = 0; jj < NP / 32; jj++) {
                    int idx = t + (jj << 5);
                    float v = pri[idx];
                    if (v < best) { best = v; bidx = idx; }
                }
#pragma unroll
                for (int o = 16; o; o >>= 1) {
                    float ov = __shfl_xor_sync(0xffffffffu, best, o);
                    int   oi = __shfl_xor_sync(0xffffffffu, bidx, o);
                    if (ov < best || (ov == best && oi < bidx)) { best = ov; bidx = oi; }
                }
                if (t == 0) { sh_minp = best; sh_mini = bidx; }
            }
            __syncthreads();
            if (sc > sh_minp) {
                poolb[sh_mini * NS + t] = summb[slot * NS + t];
                if (t == 0) pri[sh_mini] = sc;
            }
            __syncthreads();
        }
    }
    __syncthreads();
    g_pri[b * NP + t]       = pri[t];
    g_pri[b * NP + t + 256] = pri[t + 256];
    if (t == 0) g_counts[b] = sh_cnt;
}

// ---------------- generic batched transpose: src[R,C] -> dst[C,R] ----------
__global__ void transpose_kernel(const float* __restrict__ src, float* __restrict__ dst,
                                 int R, int C, long long sS, long long sD) {
    __shared__ float tile[32][33];
    src += (long long)blockIdx.z * sS;
    dst += (long long)blockIdx.z * sD;
    int r0 = blockIdx.x * 32, c0 = blockIdx.y * 32;
    int x = threadIdx.x, y = threadIdx.y;   // 32 x 8
#pragma unroll
    for (int i = 0; i < 32; i += 8)
        tile[y + i][x] = src[(long long)(r0 + y + i) * C + c0 + x];
    __syncthreads();
#pragma unroll
    for (int i = 0; i < 32; i += 8)
        dst[(long long)(c0 + y + i) * R + r0 + x] = tile[x][y + i];
}

// ---------------- masked softmax over attn rows (warp per row) -------------
__global__ void softmax_kernel() {
    int gw = (blockIdx.x * blockDim.x + threadIdx.x) >> 5;
    int lane = threadIdx.x & 31;
    if (gw >= NBT) return;
    int b = gw >> 11;
    int cnt = g_counts[b];
    float* row = g_attn + (long long)gw * NP;
    float vals[NP / 32];
    float m = -1e30f;
#pragma unroll
    for (int j = 0; j < NP / 32; j++) {
        int p = lane + (j << 5);
        float v = row[p] * 0.0625f;   // 1/sqrt(256)
        vals[j] = v;
        if (p < cnt) m = fmaxf(m, v);
    }
#pragma unroll
    for (int o = 16; o; o >>= 1) m = fmaxf(m, __shfl_xor_sync(0xffffffffu, m, o));
    float s = 0.f;
#pragma unroll
    for (int j = 0; j < NP / 32; j++) {
        int p = lane + (j << 5);
        float e = (p < cnt) ? expf(vals[j] - m) : 0.f;
        vals[j] = e;
        s += e;
    }
#pragma unroll
    for (int o = 16; o; o >>= 1) s += __shfl_xor_sync(0xffffffffu, s, o);
    float inv = (cnt > 0) ? 1.f / s : 0.f;
#pragma unroll
    for (int j = 0; j < NP / 32; j++) row[lane + (j << 5)] = vals[j] * inv;
}

// ---------------- export pool / priorities / counts into d_out -------------
__global__ void export_kernel(float* __restrict__ dst) {
    int i = blockIdx.x * blockDim.x + threadIdx.x;
    constexpr int PS = NB * NP * NS;
    if (i < PS) dst[i] = g_pool[i];
    else if (i < PS + NB * NP) dst[i] = g_pri[i - PS];
    else if (i < PS + NB * NP + NB) dst[i] = (float)g_counts[i - PS - NB * NP];
}

// ---------------- launch ----------------
extern "C" void kernel_launch(void* const* d_in, const int* in_sizes, int n_in,
                              void* d_out, int out_size) {
    const float* tokens = (const float*)d_in[0];
    const float* pool   = (const float*)d_in[1];
    const float* pri    = (const float*)d_in[2];
    const int*   counts = (const int*)d_in[3];
    const float* w1     = (const float*)d_in[4];
    const float* w2     = (const float*)d_in[5];
    const float* w_sum  = (const float*)d_in[6];
    const float* wq     = (const float*)d_in[7];
    const float* wk     = (const float*)d_in[8];
    const float* wv     = (const float*)d_in[9];
    float* out = (float*)d_out;
    (void)in_sizes; (void)n_in;

    float *ph, *pq, *pst, *psum, *ppool, *pwkT, *pwqk, *ppoolT, *pap, *pattn;
    cudaGetSymbolAddress((void**)&ph,     g_h);
    cudaGetSymbolAddress((void**)&pq,     g_q);
    cudaGetSymbolAddress((void**)&pst,    g_st);
    cudaGetSymbolAddress((void**)&psum,   g_sum);
    cudaGetSymbolAddress((void**)&ppool,  g_pool);
    cudaGetSymbolAddress((void**)&pwkT,   g_wkT);
    cudaGetSymbolAddress((void**)&pwqk,   g_wqk);
    cudaGetSymbolAddress((void**)&ppoolT, g_poolT);
    cudaGetSymbolAddress((void**)&pap,    g_ap);
    cudaGetSymbolAddress((void**)&pattn,  g_attn);

    // 1. h = tokens @ w1   [16384,1024]@[1024,256]
    sgemm128_kernel<<<dim3(NH / 128, NBT / 128, 1), 256>>>(tokens, w1, ph, NBT, NH, ND, 0, 0, 0);
    // 2. wkT = wk^T; wqk = wq @ wkT   [1024,256]@[256,256]
    transpose_kernel<<<dim3(NS / 32, NS / 32, 1), dim3(32, 8)>>>(wk, pwkT, NS, NS, 0, 0);
    sgemm128_kernel<<<dim3(NS / 128, ND / 128, 1), 256>>>(wq, pwkT, pwqk, ND, NS, NS, 0, 0, 0);
    // 3. qk = tokens @ wqk   [16384,1024]@[1024,256]
    sgemm128_kernel<<<dim3(NS / 128, NBT / 128, 1), 256>>>(tokens, pwqk, pq, NBT, NS, ND, 0, 0, 0);
    // 4. scores (fp32 fast pass)
    score_kernel<<<NBT / 8, 256>>>(w2);
    // 5. provisional sort
    sort_kernel<<<NB, 1024>>>();
    // 6. flag at-risk tokens and recompute them exactly (fp64, 4-acc)
    reset_flags_kernel<<<NBT / 256, 256>>>();
    flag_ab_kernel<<<NBT / 256, 256>>>();
    flag_c_kernel<<<dim3(NT / 256, NB), 256>>>(pri);
    compact_kernel<<<NBT / 256, 256>>>();
    recompute_kernel<<<512, 256>>>(tokens, w1, w2);
    // 7. final sort with corrected scores
    sort_kernel<<<NB, 1024>>>();
    // 8. gather top-512 tokens
    gather_kernel<<<dim3(NP, NB), 256>>>(tokens);
    // 9. summaries = sorted_tokens @ w_sum   [4096,1024]@[1024,256]
    sgemm128_kernel<<<dim3(NS / 128, NB * NP / 128, 1), 256>>>(pst, w_sum, psum, NB * NP, NS, ND, 0, 0, 0);
    // 10. sequential pool update
    update_kernel<<<NB, 256>>>(pool, pri, counts);
    // 11. poolT = pool^T per batch  [512,256] -> [256,512]
    transpose_kernel<<<dim3(NP / 32, NS / 32, NB), dim3(32, 8)>>>(ppool, ppoolT, NP, NS,
        (long long)NP * NS, (long long)NS * NP);
    // 12. attn = qk @ poolT   batched [2048,256]@[256,512]
    sgemm128_kernel<<<dim3(NP / 128, NT / 128, NB), 256>>>(pq, ppoolT, pattn, NT, NP, NS,
        (long long)NT * NS, (long long)NS * NP, (long long)NT * NP);
    // 13. masked softmax (+ 1/sqrt(S) scale, nan_to_num)
    softmax_kernel<<<NBT / 8, 256>>>();
    // 14. ap = attn @ pool   batched [2048,512]@[512,256]
    sgemm128_kernel<<<dim3(NS / 128, NT / 128, NB), 256>>>(pattn, ppool, pap, NT, NS, NP,
        (long long)NT * NP, (long long)NP * NS, (long long)NT * NS);
    // 15. retrieved = ap @ wv   [16384,256]@[256,1024] -> d_out
    sgemm128_kernel<<<dim3(ND / 128, NBT / 128, 1), 256>>>(pap, wv, out, NBT, ND, NS, 0, 0, 0);
    // 16. export pool / priorities / counts
    constexpr int RET = NBT * ND;
    constexpr int REST = NB * NP * NS + NB * NP + NB;
    if (out_size >= RET + REST)
        export_kernel<<<(REST + 255) / 256, 256>>>(out + (long long)RET);
}

// round 7
// speedup vs baseline: 1.3880x; 1.0311x over previous
#include <cuda_runtime.h>
#include <math.h>

// Problem constants
constexpr int NB  = 8;
constexpr int NT  = 2048;
constexpr int ND  = 1024;
constexpr int NP  = 512;
constexpr int NS  = 256;
constexpr int NH  = 256;
constexpr int NBT = NB * NT;      // 16384

constexpr float TAUF = 1e-5f;     // at-risk flag window (fp32 pass error ~1e-6)

// ---------------- device scratch (static allocations only) ----------------
__device__ float g_h[NBT * NH];          // tokens@w1 (pre-relu)
__device__ float g_q[NBT * NS];          // qk = tokens@(wq@wk^T)
__device__ float g_scores[NBT];
__device__ int   g_order[NBT];           // per-batch sorted token indices
__device__ float g_sscores[NBT];         // per-batch sorted scores
__device__ float g_st[NB * NP * ND];     // top-512 sorted tokens
__device__ float g_sum[NB * NP * NS];    // summaries
__device__ float g_pool[NB * NP * NS];   // updated pool
__device__ float g_pri[NB * NP];
__device__ int   g_counts[NB];
__device__ float g_wkT[NS * NS];         // wk^T
__device__ float g_wqk[ND * NS];         // wq @ wk^T
__device__ float g_poolT[NB * NS * NP];  // transposed pool
__device__ float g_ap[NBT * NS];         // attn @ pool
__device__ float g_attn[NB * NT * NP];   // attention weights
__device__ int           g_flagcnt;
__device__ int           g_flaglist[NBT];
__device__ unsigned char g_flag[NBT];

// ------- 128x128x8 double-buffered SGEMM, 8x8 microtile, 256 threads -------
__global__ __launch_bounds__(256, 2)
void sgemm128_kernel(const float* __restrict__ A, const float* __restrict__ Bm,
                     float* __restrict__ C, int M, int N, int K,
                     long long sA, long long sB, long long sC) {
    A  += (long long)blockIdx.z * sA;
    Bm += (long long)blockIdx.z * sB;
    C  += (long long)blockIdx.z * sC;
    __shared__ float As[2][8][128];    // k-major (transposed on store)
    __shared__ float Bs[2][8][128];

    const int tid  = threadIdx.x;
    const int row0 = blockIdx.y * 128, col0 = blockIdx.x * 128;
    const int ar = tid >> 1;              // 0..127
    const int ac = (tid & 1) << 2;        // 0 or 4
    const int br = tid >> 5;              // 0..7
    const int bc = (tid & 31) << 2;       // 0..124
    const float* Ap = A + (long long)(row0 + ar) * K + ac;
    const float* Bp = Bm + (long long)br * N + col0 + bc;
    const int tx = (tid & 15) << 3;
    const int ty = (tid >> 4) << 3;

    float acc[8][8] = {};
    float4 av = *(const float4*)Ap;
    float4 bv = *(const float4*)Bp;
    int buf = 0;
    As[0][ac + 0][ar] = av.x;
    As[0][ac + 1][ar] = av.y;
    As[0][ac + 2][ar] = av.z;
    As[0][ac + 3][ar] = av.w;
    *(float4*)&Bs[0][br][bc] = bv;
    __syncthreads();

    for (int k0 = 8; k0 <= K; k0 += 8) {
        if (k0 < K) {
            av = *(const float4*)(Ap + k0);
            bv = *(const float4*)(Bp + (long long)k0 * N);
        }
#pragma unroll
        for (int kk = 0; kk < 8; kk++) {
            float a[8], b[8];
            *(float4*)&a[0] = *(const float4*)&As[buf][kk][ty];
            *(float4*)&a[4] = *(const float4*)&As[buf][kk][ty + 4];
            *(float4*)&b[0] = *(const float4*)&Bs[buf][kk][tx];
            *(float4*)&b[4] = *(const float4*)&Bs[buf][kk][tx + 4];
#pragma unroll
            for (int i = 0; i < 8; i++)
#pragma unroll
                for (int j = 0; j < 8; j++)
                    acc[i][j] = fmaf(a[i], b[j], acc[i][j]);
        }
        if (k0 < K) {
            buf ^= 1;
            As[buf][ac + 0][ar] = av.x;
            As[buf][ac + 1][ar] = av.y;
            As[buf][ac + 2][ar] = av.z;
            As[buf][ac + 3][ar] = av.w;
            *(float4*)&Bs[buf][br][bc] = bv;
            __syncthreads();
        }
    }
#pragma unroll
    for (int i = 0; i < 8; i++) {
        float* crow = C + (long long)(row0 + ty + i) * N + col0 + tx;
        *(float4*)crow       = make_float4(acc[i][0], acc[i][1], acc[i][2], acc[i][3]);
        *(float4*)(crow + 4) = make_float4(acc[i][4], acc[i][5], acc[i][6], acc[i][7]);
    }
}

// ---------------- scores: sigmoid(relu(h) . w2), one warp per row ----------
__global__ void score_kernel(const float* __restrict__ w2) {
    int gw = (blockIdx.x * blockDim.x + threadIdx.x) >> 5;
    int lane = threadIdx.x & 31;
    if (gw >= NBT) return;
    const float* hr = g_h + (long long)gw * NH;
    float s = 0.f;
#pragma unroll
    for (int j = 0; j < NH / 32; j++) {
        int c = lane + (j << 5);
        float v = hr[c];
        v = fmaxf(v, 0.f);
        s = fmaf(v, w2[c], s);
    }
#pragma unroll
    for (int o = 16; o; o >>= 1) s += __shfl_xor_sync(0xffffffffu, s, o);
    if (lane == 0) g_scores[gw] = 1.0f / (1.0f + expf(-s));
}

// ---------------- per-batch bitonic sort, descending score / ascending idx --
__global__ void sort_kernel() {
    __shared__ float sk[NT];
    __shared__ int   si[NT];
    int b = blockIdx.x, t = threadIdx.x;   // 1024 threads
    sk[t]        = g_scores[b * NT + t];        si[t]        = t;
    sk[t + 1024] = g_scores[b * NT + t + 1024]; si[t + 1024] = t + 1024;
    __syncthreads();
    for (int kk = 2; kk <= NT; kk <<= 1) {
        for (int j = kk >> 1; j > 0; j >>= 1) {
            for (int i = t; i < NT; i += 1024) {
                int ixj = i ^ j;
                if (ixj > i) {
                    bool ord = ((i & kk) == 0);
                    float s1 = sk[i], s2 = sk[ixj];
                    int   i1 = si[i], i2 = si[ixj];
                    bool pre = (s2 > s1) || (s2 == s1 && i2 < i1);
                    if (pre == ord) { sk[i] = s2; sk[ixj] = s1; si[i] = i2; si[ixj] = i1; }
                }
            }
            __syncthreads();
        }
    }
    g_order[b * NT + t]          = si[t];
    g_order[b * NT + t + 1024]   = si[t + 1024];
    g_sscores[b * NT + t]        = sk[t];
    g_sscores[b * NT + t + 1024] = sk[t + 1024];
}

// ---------------- at-risk flagging ----------------
__global__ void reset_flags_kernel() {
    int i = blockIdx.x * blockDim.x + threadIdx.x;
    if (i < NBT) g_flag[i] = 0;
    if (i == 0) g_flagcnt = 0;
}

__global__ void flag_ab_kernel() {
    int i = blockIdx.x * blockDim.x + threadIdx.x;   // global sorted position
    if (i >= NBT) return;
    int b = i >> 11, p = i & (NT - 1);
    float s = g_sscores[i];
    if (fabsf(s - 0.5f) < TAUF) g_flag[b * NT + g_order[i]] = 1;
    if (p + 1 < NT) {
        float s2 = g_sscores[i + 1];
        if (fabsf(s - s2) < TAUF) {
            g_flag[b * NT + g_order[i]] = 1;
            g_flag[b * NT + g_order[i + 1]] = 1;
        }
    }
}

__global__ void flag_c_kernel(const float* __restrict__ pri_in) {
    __shared__ float pr[NP];
    int b = blockIdx.y;
    for (int i = threadIdx.x; i < NP; i += blockDim.x) pr[i] = pri_in[b * NP + i];
    __syncthreads();
    int t = blockIdx.x * blockDim.x + threadIdx.x;
    if (t >= NT) return;
    float s = g_scores[b * NT + t];
    bool hit = false;
#pragma unroll 8
    for (int i = 0; i < NP; i++) hit |= (fabsf(s - pr[i]) < TAUF);
    if (hit) g_flag[b * NT + t] = 1;
}

__global__ void compact_kernel() {
    int i = blockIdx.x * blockDim.x + threadIdx.x;
    if (i < NBT && g_flag[i]) {
        int pos = atomicAdd(&g_flagcnt, 1);
        g_flaglist[pos] = i;
    }
}

// exact fp64 recompute of flagged tokens' scores, 4 independent accumulators
__global__ void recompute_kernel(const float* __restrict__ tokens,
                                 const float* __restrict__ w1,
                                 const float* __restrict__ w2) {
    __shared__ double red[256];
    int j = threadIdx.x;   // 256 threads = H columns
    int n = g_flagcnt;
    if (blockIdx.x >= n) return;
    for (int li = blockIdx.x; li < n; li += gridDim.x) {
        int g = g_flaglist[li];
        const float* x = tokens + (long long)g * ND;
        const float* wcol = w1 + j;
        double a0 = 0.0, a1 = 0.0, a2 = 0.0, a3 = 0.0;
        for (int d = 0; d < ND; d += 4) {
            a0 += (double)x[d + 0] * (double)wcol[(long long)(d + 0) * NH];
            a1 += (double)x[d + 1] * (double)wcol[(long long)(d + 1) * NH];
            a2 += (double)x[d + 2] * (double)wcol[(long long)(d + 2) * NH];
            a3 += (double)x[d + 3] * (double)wcol[(long long)(d + 3) * NH];
        }
        double acc = (a0 + a1) + (a2 + a3);
        float hf = fmaxf((float)acc, 0.0f);      // round to fp32, relu
        red[j] = (double)hf * (double)w2[j];
        __syncthreads();
        for (int s = 128; s; s >>= 1) {
            if (j < s) red[j] += red[j + s];
            __syncthreads();
        }
        if (j == 0) {
            double z = red[0];
            g_scores[g] = (float)(1.0 / (1.0 + exp(-z)));
        }
        __syncthreads();
    }
}

// ---------------- gather top-512 sorted tokens ----------------
__global__ void gather_kernel(const float* __restrict__ tokens) {
    int b = blockIdx.y, slot = blockIdx.x;
    int src = g_order[b * NT + slot];
    const float4* s4 = (const float4*)(tokens + ((long long)b * NT + src) * ND);
    float4* d4 = (float4*)(g_st + ((long long)b * NP + slot) * ND);
    d4[threadIdx.x] = s4[threadIdx.x];
}

// ---------------- wide pool copy (input pool -> working pool) --------------
__global__ void copy_pool_kernel(const float* __restrict__ pool_in) {
    int i = blockIdx.x * blockDim.x + threadIdx.x;   // float4 index
    ((float4*)g_pool)[i] = ((const float4*)pool_in)[i];
}

// ---- sequential pool update with two-level incremental argmin -------------
// 256 threads per batch. Groups of 32 priorities; per-slot we rescan only the
// modified group (warp reduce) + reduce 16 group mins. Tie-breaking = first
// (lowest) index, matching jnp.argmin. Early break: sorted scores descending,
// once score <= 0.5 no later slot can act (exact reference semantics).
__global__ void update_kernel(const float* __restrict__ pri_in,
                              const int* __restrict__ counts_in) {
    int b = blockIdx.x, t = threadIdx.x;   // 256 threads
    int lane = t & 31, wid = t >> 5;
    __shared__ float pri[NP];
    __shared__ float gmin[16];
    __shared__ int   gidx[16];
    __shared__ int   sh_rep;
    pri[t]       = pri_in[b * NP + t];
    pri[t + 256] = pri_in[b * NP + t + 256];
    __syncthreads();
    // init group mins: 8 warps x 2 groups
    for (int g = wid; g < 16; g += 8) {
        float v = pri[(g << 5) + lane];
        int ix = (g << 5) + lane;
#pragma unroll
        for (int o = 16; o; o >>= 1) {
            float ov = __shfl_xor_sync(0xffffffffu, v, o);
            int   oi = __shfl_xor_sync(0xffffffffu, ix, o);
            if (ov < v || (ov == v && oi < ix)) { v = ov; ix = oi; }
        }
        if (lane == 0) { gmin[g] = v; gidx[g] = ix; }
    }
    __syncthreads();

    int cnt = counts_in[b];                  // uniform across block
    float*       poolb = g_pool + (long long)b * NP * NS;
    const float* summb = g_sum + (long long)b * NP * NS;
    const float* ss    = g_sscores + b * NT;

    for (int slot = 0; slot < NP; slot++) {
        float sc = ss[slot];
        if (!(sc > 0.5f)) break;             // sorted descending -> done
        int ins = -1;
        if (cnt < NP) { ins = cnt; cnt++; }  // uniform
        if (wid == 0) {
            int rep = -1;
            if (ins >= 0) {
                if (lane == 0) pri[ins] = sc;
                __syncwarp();
                int g = ins >> 5;            // rescan modified group
                float v = pri[(g << 5) + lane];
                int ix = (g << 5) + lane;
#pragma unroll
                for (int o = 16; o; o >>= 1) {
                    float ov = __shfl_xor_sync(0xffffffffu, v, o);
                    int   oi = __shfl_xor_sync(0xffffffffu, ix, o);
                    if (ov < v || (ov == v && oi < ix)) { v = ov; ix = oi; }
                }
                if (lane == 0) { gmin[g] = v; gidx[g] = ix; }
                __syncwarp();
            }
            if (cnt >= NP) {                 // replace-min (post-insert state)
                float v = (lane < 16) ? gmin[lane] : 3.4e38f;
                int  ix = (lane < 16) ? gidx[lane] : 0x7fffffff;
#pragma unroll
                for (int o = 16; o; o >>= 1) {
                    float ov = __shfl_xor_sync(0xffffffffu, v, o);
                    int   oi = __shfl_xor_sync(0xffffffffu, ix, o);
                    if (ov < v || (ov == v && oi < ix)) { v = ov; ix = oi; }
                }
                if (sc > v) {
                    rep = ix;
                    if (lane == 0) pri[rep] = sc;
                    __syncwarp();
                    int g = rep >> 5;        // rescan modified group
                    float vv = pri[(g << 5) + lane];
                    int   ii = (g << 5) + lane;
#pragma unroll
                    for (int o = 16; o; o >>= 1) {
                        float ov = __shfl_xor_sync(0xffffffffu, vv, o);
                        int   oi = __shfl_xor_sync(0xffffffffu, ii, o);
                        if (ov < vv || (ov == vv && oi < ii)) { vv = ov; ii = oi; }
                    }
                    if (lane == 0) { gmin[g] = vv; gidx[g] = ii; }
                    __syncwarp();
                }
            }
            if (lane == 0) sh_rep = rep;
        }
        __syncthreads();
        int rep = sh_rep;
        const float* srow = summb + slot * NS;
        if (ins >= 0) poolb[ins * NS + t] = srow[t];
        if (rep >= 0) poolb[rep * NS + t] = srow[t];
        __syncthreads();
    }
    __syncthreads();
    g_pri[b * NP + t]       = pri[t];
    g_pri[b * NP + t + 256] = pri[t + 256];
    if (t == 0) g_counts[b] = cnt;
}

// ---------------- generic batched transpose: src[R,C] -> dst[C,R] ----------
__global__ void transpose_kernel(const float* __restrict__ src, float* __restrict__ dst,
                                 int R, int C, long long sS, long long sD) {
    __shared__ float tile[32][33];
    src += (long long)blockIdx.z * sS;
    dst += (long long)blockIdx.z * sD;
    int r0 = blockIdx.x * 32, c0 = blockIdx.y * 32;
    int x = threadIdx.x, y = threadIdx.y;   // 32 x 8
#pragma unroll
    for (int i = 0; i < 32; i += 8)
        tile[y + i][x] = src[(long long)(r0 + y + i) * C + c0 + x];
    __syncthreads();
#pragma unroll
    for (int i = 0; i < 32; i += 8)
        dst[(long long)(c0 + y + i) * R + r0 + x] = tile[x][y + i];
}

// ---------------- masked softmax over attn rows (warp per row) -------------
__global__ void softmax_kernel() {
    int gw = (blockIdx.x * blockDim.x + threadIdx.x) >> 5;
    int lane = threadIdx.x & 31;
    if (gw >= NBT) return;
    int b = gw >> 11;
    int cnt = g_counts[b];
    float* row = g_attn + (long long)gw * NP;
    float vals[NP / 32];
    float m = -1e30f;
#pragma unroll
    for (int j = 0; j < NP / 32; j++) {
        int p = lane + (j << 5);
        float v = row[p] * 0.0625f;   // 1/sqrt(256)
        vals[j] = v;
        if (p < cnt) m = fmaxf(m, v);
    }
#pragma unroll
    for (int o = 16; o; o >>= 1) m = fmaxf(m, __shfl_xor_sync(0xffffffffu, m, o));
    float s = 0.f;
#pragma unroll
    for (int j = 0; j < NP / 32; j++) {
        int p = lane + (j << 5);
        float e = (p < cnt) ? expf(vals[j] - m) : 0.f;
        vals[j] = e;
        s += e;
    }
#pragma unroll
    for (int o = 16; o; o >>= 1) s += __shfl_xor_sync(0xffffffffu, s, o);
    float inv = (cnt > 0) ? 1.f / s : 0.f;
#pragma unroll
    for (int j = 0; j < NP / 32; j++) row[lane + (j << 5)] = vals[j] * inv;
}

// ---------------- export pool / priorities / counts into d_out -------------
__global__ void export_kernel(float* __restrict__ dst) {
    int i = blockIdx.x * blockDim.x + threadIdx.x;
    constexpr int PS = NB * NP * NS;
    if (i < PS) dst[i] = g_pool[i];
    else if (i < PS + NB * NP) dst[i] = g_pri[i - PS];
    else if (i < PS + NB * NP + NB) dst[i] = (float)g_counts[i - PS - NB * NP];
}

// ---------------- launch ----------------
extern "C" void kernel_launch(void* const* d_in, const int* in_sizes, int n_in,
                              void* d_out, int out_size) {
    const float* tokens = (const float*)d_in[0];
    const float* pool   = (const float*)d_in[1];
    const float* pri    = (const float*)d_in[2];
    const int*   counts = (const int*)d_in[3];
    const float* w1     = (const float*)d_in[4];
    const float* w2     = (const float*)d_in[5];
    const float* w_sum  = (const float*)d_in[6];
    const float* wq     = (const float*)d_in[7];
    const float* wk     = (const float*)d_in[8];
    const float* wv     = (const float*)d_in[9];
    float* out = (float*)d_out;
    (void)in_sizes; (void)n_in;

    float *ph, *pq, *pst, *psum, *ppool, *pwkT, *pwqk, *ppoolT, *pap, *pattn;
    cudaGetSymbolAddress((void**)&ph,     g_h);
    cudaGetSymbolAddress((void**)&pq,     g_q);
    cudaGetSymbolAddress((void**)&pst,    g_st);
    cudaGetSymbolAddress((void**)&psum,   g_sum);
    cudaGetSymbolAddress((void**)&ppool,  g_pool);
    cudaGetSymbolAddress((void**)&pwkT,   g_wkT);
    cudaGetSymbolAddress((void**)&pwqk,   g_wqk);
    cudaGetSymbolAddress((void**)&ppoolT, g_poolT);
    cudaGetSymbolAddress((void**)&pap,    g_ap);
    cudaGetSymbolAddress((void**)&pattn,  g_attn);

    // side stream for the independent qk chain (created per call, leaked —
    // host-side cost only; graph replays never rerun this function)
    cudaStream_t s1;
    cudaStreamCreateWithFlags(&s1, cudaStreamNonBlocking);
    cudaEvent_t evFork, evQK;
    cudaEventCreateWithFlags(&evFork, cudaEventDisableTiming);
    cudaEventCreateWithFlags(&evQK, cudaEventDisableTiming);

    cudaEventRecord(evFork, 0);
    cudaStreamWaitEvent(s1, evFork, 0);
    // s1: wkT = wk^T; wqk = wq @ wkT; qk = tokens @ wqk
    transpose_kernel<<<dim3(NS / 32, NS / 32, 1), dim3(32, 8), 0, s1>>>(wk, pwkT, NS, NS, 0, 0);
    sgemm128_kernel<<<dim3(NS / 128, ND / 128, 1), 256, 0, s1>>>(wq, pwkT, pwqk, ND, NS, NS, 0, 0, 0);
    sgemm128_kernel<<<dim3(NS / 128, NBT / 128, 1), 256, 0, s1>>>(tokens, pwqk, pq, NBT, NS, ND, 0, 0, 0);
    cudaEventRecord(evQK, s1);

    // main: score path
    sgemm128_kernel<<<dim3(NH / 128, NBT / 128, 1), 256>>>(tokens, w1, ph, NBT, NH, ND, 0, 0, 0);
    score_kernel<<<NBT / 8, 256>>>(w2);
    sort_kernel<<<NB, 1024>>>();
    reset_flags_kernel<<<NBT / 256, 256>>>();
    flag_ab_kernel<<<NBT / 256, 256>>>();
    flag_c_kernel<<<dim3(NT / 256, NB), 256>>>(pri);
    compact_kernel<<<NBT / 256, 256>>>();
    recompute_kernel<<<512, 256>>>(tokens, w1, w2);
    sort_kernel<<<NB, 1024>>>();
    gather_kernel<<<dim3(NP, NB), 256>>>(tokens);
    // summaries = sorted_tokens @ w_sum
    sgemm128_kernel<<<dim3(NS / 128, NB * NP / 128, 1), 256>>>(pst, w_sum, psum, NB * NP, NS, ND, 0, 0, 0);
    // pool copy (wide) + sequential per-batch update
    copy_pool_kernel<<<(NB * NP * NS / 4) / 256, 256>>>(pool);
    update_kernel<<<NB, 256>>>(pri, counts);
    // poolT = pool^T per batch
    transpose_kernel<<<dim3(NP / 32, NS / 32, NB), dim3(32, 8)>>>(ppool, ppoolT, NP, NS,
        (long long)NP * NS, (long long)NS * NP);
    // join qk chain, then attn = qk @ poolT
    cudaStreamWaitEvent(0, evQK, 0);
    sgemm128_kernel<<<dim3(NP / 128, NT / 128, NB), 256>>>(pq, ppoolT, pattn, NT, NP, NS,
        (long long)NT * NS, (long long)NS * NP, (long long)NT * NP);
    softmax_kernel<<<NBT / 8, 256>>>();
    // ap = attn @ pool ; retrieved = ap @ wv
    sgemm128_kernel<<<dim3(NS / 128, NT / 128, NB), 256>>>(pattn, ppool, pap, NT, NS, NP,
        (long long)NT * NP, (long long)NP * NS, (long long)NT * NS);
    sgemm128_kernel<<<dim3(ND / 128, NBT / 128, 1), 256>>>(pap, wv, out, NBT, ND, NS, 0, 0, 0);
    // export pool / priorities / counts
    constexpr int RET = NBT * ND;
    constexpr int REST = NB * NP * NS + NB * NP + NB;
    if (out_size >= RET + REST)
        export_kernel<<<(REST + 255) / 256, 256>>>(out + (long long)RET);
}

// round 8
// speedup vs baseline: 1.4993x; 1.0802x over previous
#include <cuda_runtime.h>
#include <math.h>

// Problem constants
constexpr int NB  = 8;
constexpr int NT  = 2048;
constexpr int ND  = 1024;
constexpr int NP  = 512;
constexpr int NS  = 256;
constexpr int NH  = 256;
constexpr int NBT = NB * NT;      // 16384

constexpr float TAUF = 1e-5f;     // at-risk flag window (fp32 pass error ~1e-6)

// ---------------- device scratch (static allocations only) ----------------
__device__ float g_h[NBT * NH];          // tokens@w1 (pre-relu)
__device__ float g_q[NBT * NS];          // qk = tokens@(wq@wk^T)
__device__ float g_scores[NBT];
__device__ int   g_order[NBT];           // per-batch sorted token indices
__device__ float g_sscores[NBT];         // per-batch sorted scores
__device__ float g_st[NB * NP * ND];     // top-512 sorted tokens
__device__ float g_sum[NB * NP * NS];    // summaries
__device__ float g_pool[NB * NP * NS];   // updated pool
__device__ float g_pri[NB * NP];
__device__ int   g_counts[NB];
__device__ float g_wkT[NS * NS];         // wk^T
__device__ float g_wqk[ND * NS];         // wq @ wk^T
__device__ float g_poolT[NB * NS * NP];  // transposed pool
__device__ float g_ap[NBT * NS];         // attn @ pool
__device__ float g_attn[NB * NT * NP];   // attention weights
__device__ int           g_flagcnt;
__device__ int           g_flaglist[NBT];
__device__ unsigned char g_flag[NBT];

// ------- 128x128x16 double-buffered SGEMM, 8x8 microtile, 256 threads ------
// C = A(MxK) @ B(KxN), row-major; M%128==0, N%128==0, K%16==0 (all shapes here).
__global__ __launch_bounds__(256, 2)
void sgemm128_kernel(const float* __restrict__ A, const float* __restrict__ Bm,
                     float* __restrict__ C, int M, int N, int K,
                     long long sA, long long sB, long long sC) {
    A  += (long long)blockIdx.z * sA;
    Bm += (long long)blockIdx.z * sB;
    C  += (long long)blockIdx.z * sC;
    __shared__ float As[2][16][128];   // k-major (transposed on store)
    __shared__ float Bs[2][16][128];

    const int tid  = threadIdx.x;
    const int row0 = blockIdx.y * 128, col0 = blockIdx.x * 128;
    // A tile load: 128 rows x 16 cols; each thread two float4
    const int ar = tid >> 1;              // 0..127
    const int ac = (tid & 1) << 3;        // 0 or 8
    // B tile load: 16 rows x 128 cols; each thread two float4
    const int br = tid >> 4;              // 0..15
    const int bc = (tid & 15) << 3;       // 0..120
    const float* Ap = A + (long long)(row0 + ar) * K + ac;
    const float* Bp = Bm + (long long)br * N + col0 + bc;
    const int tx = (tid & 15) << 3;
    const int ty = (tid >> 4) << 3;

    float acc[8][8] = {};
    float4 av0 = *(const float4*)Ap;
    float4 av1 = *(const float4*)(Ap + 4);
    float4 bv0 = *(const float4*)Bp;
    float4 bv1 = *(const float4*)(Bp + 4);
    int buf = 0;
    As[0][ac + 0][ar] = av0.x; As[0][ac + 1][ar] = av0.y;
    As[0][ac + 2][ar] = av0.z; As[0][ac + 3][ar] = av0.w;
    As[0][ac + 4][ar] = av1.x; As[0][ac + 5][ar] = av1.y;
    As[0][ac + 6][ar] = av1.z; As[0][ac + 7][ar] = av1.w;
    *(float4*)&Bs[0][br][bc]     = bv0;
    *(float4*)&Bs[0][br][bc + 4] = bv1;
    __syncthreads();

    for (int k0 = 16; k0 <= K; k0 += 16) {
        if (k0 < K) {                       // prefetch next tile into regs
            av0 = *(const float4*)(Ap + k0);
            av1 = *(const float4*)(Ap + k0 + 4);
            bv0 = *(const float4*)(Bp + (long long)k0 * N);
            bv1 = *(const float4*)(Bp + (long long)k0 * N + 4);
        }
#pragma unroll
        for (int kk = 0; kk < 16; kk++) {
            float a[8], b[8];
            *(float4*)&a[0] = *(const float4*)&As[buf][kk][ty];
            *(float4*)&a[4] = *(const float4*)&As[buf][kk][ty + 4];
            *(float4*)&b[0] = *(const float4*)&Bs[buf][kk][tx];
            *(float4*)&b[4] = *(const float4*)&Bs[buf][kk][tx + 4];
#pragma unroll
            for (int i = 0; i < 8; i++)
#pragma unroll
                for (int j = 0; j < 8; j++)
                    acc[i][j] = fmaf(a[i], b[j], acc[i][j]);
        }
        if (k0 < K) {
            buf ^= 1;
            As[buf][ac + 0][ar] = av0.x; As[buf][ac + 1][ar] = av0.y;
            As[buf][ac + 2][ar] = av0.z; As[buf][ac + 3][ar] = av0.w;
            As[buf][ac + 4][ar] = av1.x; As[buf][ac + 5][ar] = av1.y;
            As[buf][ac + 6][ar] = av1.z; As[buf][ac + 7][ar] = av1.w;
            *(float4*)&Bs[buf][br][bc]     = bv0;
            *(float4*)&Bs[buf][br][bc + 4] = bv1;
            __syncthreads();
        }
    }
#pragma unroll
    for (int i = 0; i < 8; i++) {
        float* crow = C + (long long)(row0 + ty + i) * N + col0 + tx;
        *(float4*)crow       = make_float4(acc[i][0], acc[i][1], acc[i][2], acc[i][3]);
        *(float4*)(crow + 4) = make_float4(acc[i][4], acc[i][5], acc[i][6], acc[i][7]);
    }
}

// ---------------- scores: sigmoid(relu(h) . w2), one warp per row ----------
__global__ void score_kernel(const float* __restrict__ w2) {
    int gw = (blockIdx.x * blockDim.x + threadIdx.x) >> 5;
    int lane = threadIdx.x & 31;
    if (gw >= NBT) return;
    const float* hr = g_h + (long long)gw * NH;
    float s = 0.f;
#pragma unroll
    for (int j = 0; j < NH / 32; j++) {
        int c = lane + (j << 5);
        float v = hr[c];
        v = fmaxf(v, 0.f);
        s = fmaf(v, w2[c], s);
    }
#pragma unroll
    for (int o = 16; o; o >>= 1) s += __shfl_xor_sync(0xffffffffu, s, o);
    if (lane == 0) g_scores[gw] = 1.0f / (1.0f + expf(-s));
}

// ---------------- per-batch bitonic sort, descending score / ascending idx --
__global__ void sort_kernel() {
    __shared__ float sk[NT];
    __shared__ int   si[NT];
    int b = blockIdx.x, t = threadIdx.x;   // 1024 threads
    sk[t]        = g_scores[b * NT + t];        si[t]        = t;
    sk[t + 1024] = g_scores[b * NT + t + 1024]; si[t + 1024] = t + 1024;
    __syncthreads();
    for (int kk = 2; kk <= NT; kk <<= 1) {
        for (int j = kk >> 1; j > 0; j >>= 1) {
            for (int i = t; i < NT; i += 1024) {
                int ixj = i ^ j;
                if (ixj > i) {
                    bool ord = ((i & kk) == 0);
                    float s1 = sk[i], s2 = sk[ixj];
                    int   i1 = si[i], i2 = si[ixj];
                    bool pre = (s2 > s1) || (s2 == s1 && i2 < i1);
                    if (pre == ord) { sk[i] = s2; sk[ixj] = s1; si[i] = i2; si[ixj] = i1; }
                }
            }
            __syncthreads();
        }
    }
    g_order[b * NT + t]          = si[t];
    g_order[b * NT + t + 1024]   = si[t + 1024];
    g_sscores[b * NT + t]        = sk[t];
    g_sscores[b * NT + t + 1024] = sk[t + 1024];
}

// ---------------- at-risk flagging ----------------
__global__ void reset_flags_kernel() {
    int i = blockIdx.x * blockDim.x + threadIdx.x;
    if (i < NBT) g_flag[i] = 0;
    if (i == 0) g_flagcnt = 0;
}

__global__ void flag_ab_kernel() {
    int i = blockIdx.x * blockDim.x + threadIdx.x;   // global sorted position
    if (i >= NBT) return;
    int b = i >> 11, p = i & (NT - 1);
    float s = g_sscores[i];
    if (fabsf(s - 0.5f) < TAUF) g_flag[b * NT + g_order[i]] = 1;
    if (p + 1 < NT) {
        float s2 = g_sscores[i + 1];
        if (fabsf(s - s2) < TAUF) {
            g_flag[b * NT + g_order[i]] = 1;
            g_flag[b * NT + g_order[i + 1]] = 1;
        }
    }
}

__global__ void flag_c_kernel(const float* __restrict__ pri_in) {
    __shared__ float pr[NP];
    int b = blockIdx.y;
    for (int i = threadIdx.x; i < NP; i += blockDim.x) pr[i] = pri_in[b * NP + i];
    __syncthreads();
    int t = blockIdx.x * blockDim.x + threadIdx.x;
    if (t >= NT) return;
    float s = g_scores[b * NT + t];
    bool hit = false;
#pragma unroll 8
    for (int i = 0; i < NP; i++) hit |= (fabsf(s - pr[i]) < TAUF);
    if (hit) g_flag[b * NT + t] = 1;
}

__global__ void compact_kernel() {
    int i = blockIdx.x * blockDim.x + threadIdx.x;
    if (i < NBT && g_flag[i]) {
        int pos = atomicAdd(&g_flagcnt, 1);
        g_flaglist[pos] = i;
    }
}

// ---- double-float helpers (compensated fp32; error ~ n*eps^2 ~ 6e-14) ----
__device__ __forceinline__ void twoProd(float a, float b, float& p, float& e) {
    p = a * b;
    e = fmaf(a, b, -p);
}
__device__ __forceinline__ void twoSum(float a, float b, float& s, float& e) {
    s = a + b;
    float bb = s - a;
    e = (a - (s - bb)) + (b - bb);
}

// high-precision recompute of flagged tokens' scores on the fp32 pipe
__global__ void recompute_kernel(const float* __restrict__ tokens,
                                 const float* __restrict__ w1,
                                 const float* __restrict__ w2) {
    __shared__ double red[256];
    int j = threadIdx.x;   // 256 threads = H columns
    int n = g_flagcnt;
    if (blockIdx.x >= n) return;
    for (int li = blockIdx.x; li < n; li += gridDim.x) {
        int g = g_flaglist[li];
        const float* x = tokens + (long long)g * ND;
        const float* wcol = w1 + j;
        float hi = 0.f, lo = 0.f;
        for (int d = 0; d < ND; d++) {
            float p, pe, t;
            twoProd(x[d], wcol[(long long)d * NH], p, pe);
            twoSum(hi, p, hi, t);
            lo += t + pe;
        }
        double hd = (double)hi + (double)lo;
        float hf = fmaxf((float)hd, 0.0f);        // round to fp32, relu
        red[j] = (double)hf * (double)w2[j];
        __syncthreads();
        for (int s = 128; s; s >>= 1) {
            if (j < s) red[j] += red[j + s];
            __syncthreads();
        }
        if (j == 0) {
            double z = red[0];
            g_scores[g] = (float)(1.0 / (1.0 + exp(-z)));
        }
        __syncthreads();
    }
}

// ---------------- gather top-512 sorted tokens ----------------
__global__ void gather_kernel(const float* __restrict__ tokens) {
    int b = blockIdx.y, slot = blockIdx.x;
    int src = g_order[b * NT + slot];
    const float4* s4 = (const float4*)(tokens + ((long long)b * NT + src) * ND);
    float4* d4 = (float4*)(g_st + ((long long)b * NP + slot) * ND);
    d4[threadIdx.x] = s4[threadIdx.x];
}

// ---------------- wide pool copy (input pool -> working pool) --------------
__global__ void copy_pool_kernel(const float* __restrict__ pool_in) {
    int i = blockIdx.x * blockDim.x + threadIdx.x;   // float4 index
    ((float4*)g_pool)[i] = ((const float4*)pool_in)[i];
}

// ---- sequential pool update with two-level incremental argmin -------------
__global__ void update_kernel(const float* __restrict__ pri_in,
                              const int* __restrict__ counts_in) {
    int b = blockIdx.x, t = threadIdx.x;   // 256 threads
    int lane = t & 31, wid = t >> 5;
    __shared__ float pri[NP];
    __shared__ float gmin[16];
    __shared__ int   gidx[16];
    __shared__ int   sh_rep;
    pri[t]       = pri_in[b * NP + t];
    pri[t + 256] = pri_in[b * NP + t + 256];
    __syncthreads();
    for (int g = wid; g < 16; g += 8) {
        float v = pri[(g << 5) + lane];
        int ix = (g << 5) + lane;
#pragma unroll
        for (int o = 16; o; o >>= 1) {
            float ov = __shfl_xor_sync(0xffffffffu, v, o);
            int   oi = __shfl_xor_sync(0xffffffffu, ix, o);
            if (ov < v || (ov == v && oi < ix)) { v = ov; ix = oi; }
        }
        if (lane == 0) { gmin[g] = v; gidx[g] = ix; }
    }
    __syncthreads();

    int cnt = counts_in[b];                  // uniform across block
    float*       poolb = g_pool + (long long)b * NP * NS;
    const float* summb = g_sum + (long long)b * NP * NS;
    const float* ss    = g_sscores + b * NT;

    for (int slot = 0; slot < NP; slot++) {
        float sc = ss[slot];
        if (!(sc > 0.5f)) break;             // sorted descending -> done
        int ins = -1;
        if (cnt < NP) { ins = cnt; cnt++; }  // uniform
        if (wid == 0) {
            int rep = -1;
            if (ins >= 0) {
                if (lane == 0) pri[ins] = sc;
                __syncwarp();
                int g = ins >> 5;
                float v = pri[(g << 5) + lane];
                int ix = (g << 5) + lane;
#pragma unroll
                for (int o = 16; o; o >>= 1) {
                    float ov = __shfl_xor_sync(0xffffffffu, v, o);
                    int   oi = __shfl_xor_sync(0xffffffffu, ix, o);
                    if (ov < v || (ov == v && oi < ix)) { v = ov; ix = oi; }
                }
                if (lane == 0) { gmin[g] = v; gidx[g] = ix; }
                __syncwarp();
            }
            if (cnt >= NP) {                 // replace-min (post-insert state)
                float v = (lane < 16) ? gmin[lane] : 3.4e38f;
                int  ix = (lane < 16) ? gidx[lane] : 0x7fffffff;
#pragma unroll
                for (int o = 16; o; o >>= 1) {
                    float ov = __shfl_xor_sync(0xffffffffu, v, o);
                    int   oi = __shfl_xor_sync(0xffffffffu, ix, o);
                    if (ov < v || (ov == v && oi < ix)) { v = ov; ix = oi; }
                }
                if (sc > v) {
                    rep = ix;
                    if (lane == 0) pri[rep] = sc;
                    __syncwarp();
                    int g = rep >> 5;
                    float vv = pri[(g << 5) + lane];
                    int   ii = (g << 5) + lane;
#pragma unroll
                    for (int o = 16; o; o >>= 1) {
                        float ov = __shfl_xor_sync(0xffffffffu, vv, o);
                        int   oi = __shfl_xor_sync(0xffffffffu, ii, o);
                        if (ov < vv || (ov == vv && oi < ii)) { vv = ov; ii = oi; }
                    }
                    if (lane == 0) { gmin[g] = vv; gidx[g] = ii; }
                    __syncwarp();
                }
            }
            if (lane == 0) sh_rep = rep;
        }
        __syncthreads();
        int rep = sh_rep;
        const float* srow = summb + slot * NS;
        if (ins >= 0) poolb[ins * NS + t] = srow[t];
        if (rep >= 0) poolb[rep * NS + t] = srow[t];
        __syncthreads();
    }
    __syncthreads();
    g_pri[b * NP + t]       = pri[t];
    g_pri[b * NP + t + 256] = pri[t + 256];
    if (t == 0) g_counts[b] = cnt;
}

// ---------------- generic batched transpose: src[R,C] -> dst[C,R] ----------
__global__ void transpose_kernel(const float* __restrict__ src, float* __restrict__ dst,
                                 int R, int C, long long sS, long long sD) {
    __shared__ float tile[32][33];
    src += (long long)blockIdx.z * sS;
    dst += (long long)blockIdx.z * sD;
    int r0 = blockIdx.x * 32, c0 = blockIdx.y * 32;
    int x = threadIdx.x, y = threadIdx.y;   // 32 x 8
#pragma unroll
    for (int i = 0; i < 32; i += 8)
        tile[y + i][x] = src[(long long)(r0 + y + i) * C + c0 + x];
    __syncthreads();
#pragma unroll
    for (int i = 0; i < 32; i += 8)
        dst[(long long)(c0 + y + i) * R + r0 + x] = tile[x][y + i];
}

// ---------------- masked softmax over attn rows (warp per row) -------------
__global__ void softmax_kernel() {
    int gw = (blockIdx.x * blockDim.x + threadIdx.x) >> 5;
    int lane = threadIdx.x & 31;
    if (gw >= NBT) return;
    int b = gw >> 11;
    int cnt = g_counts[b];
    float* row = g_attn + (long long)gw * NP;
    float vals[NP / 32];
    float m = -1e30f;
#pragma unroll
    for (int j = 0; j < NP / 32; j++) {
        int p = lane + (j << 5);
        float v = row[p] * 0.0625f;   // 1/sqrt(256)
        vals[j] = v;
        if (p < cnt) m = fmaxf(m, v);
    }
#pragma unroll
    for (int o = 16; o; o >>= 1) m = fmaxf(m, __shfl_xor_sync(0xffffffffu, m, o));
    float s = 0.f;
#pragma unroll
    for (int j = 0; j < NP / 32; j++) {
        int p = lane + (j << 5);
        float e = (p < cnt) ? expf(vals[j] - m) : 0.f;
        vals[j] = e;
        s += e;
    }
#pragma unroll
    for (int o = 16; o; o >>= 1) s += __shfl_xor_sync(0xffffffffu, s, o);
    float inv = (cnt > 0) ? 1.f / s : 0.f;
#pragma unroll
    for (int j = 0; j < NP / 32; j++) row[lane + (j << 5)] = vals[j] * inv;
}

// ---------------- export pool / priorities / counts into d_out -------------
__global__ void export_kernel(float* __restrict__ dst) {
    int i = blockIdx.x * blockDim.x + threadIdx.x;
    constexpr int PS = NB * NP * NS;
    if (i < PS) dst[i] = g_pool[i];
    else if (i < PS + NB * NP) dst[i] = g_pri[i - PS];
    else if (i < PS + NB * NP + NB) dst[i] = (float)g_counts[i - PS - NB * NP];
}

// ---------------- launch ----------------
extern "C" void kernel_launch(void* const* d_in, const int* in_sizes, int n_in,
                              void* d_out, int out_size) {
    const float* tokens = (const float*)d_in[0];
    const float* pool   = (const float*)d_in[1];
    const float* pri    = (const float*)d_in[2];
    const int*   counts = (const int*)d_in[3];
    const float* w1     = (const float*)d_in[4];
    const float* w2     = (const float*)d_in[5];
    const float* w_sum  = (const float*)d_in[6];
    const float* wq     = (const float*)d_in[7];
    const float* wk     = (const float*)d_in[8];
    const float* wv     = (const float*)d_in[9];
    float* out = (float*)d_out;
    (void)in_sizes; (void)n_in;

    float *ph, *pq, *pst, *psum, *ppool, *pwkT, *pwqk, *ppoolT, *pap, *pattn;
    cudaGetSymbolAddress((void**)&ph,     g_h);
    cudaGetSymbolAddress((void**)&pq,     g_q);
    cudaGetSymbolAddress((void**)&pst,    g_st);
    cudaGetSymbolAddress((void**)&psum,   g_sum);
    cudaGetSymbolAddress((void**)&ppool,  g_pool);
    cudaGetSymbolAddress((void**)&pwkT,   g_wkT);
    cudaGetSymbolAddress((void**)&pwqk,   g_wqk);
    cudaGetSymbolAddress((void**)&ppoolT, g_poolT);
    cudaGetSymbolAddress((void**)&pap,    g_ap);
    cudaGetSymbolAddress((void**)&pattn,  g_attn);

    // side stream for the independent qk chain
    cudaStream_t s1;
    cudaStreamCreateWithFlags(&s1, cudaStreamNonBlocking);
    cudaEvent_t evFork, evQK;
    cudaEventCreateWithFlags(&evFork, cudaEventDisableTiming);
    cudaEventCreateWithFlags(&evQK, cudaEventDisableTiming);

    cudaEventRecord(evFork, 0);
    cudaStreamWaitEvent(s1, evFork, 0);
    // s1: wkT = wk^T; wqk = wq @ wkT; qk = tokens @ wqk
    transpose_kernel<<<dim3(NS / 32, NS / 32, 1), dim3(32, 8), 0, s1>>>(wk, pwkT, NS, NS, 0, 0);
    sgemm128_kernel<<<dim3(NS / 128, ND / 128, 1), 256, 0, s1>>>(wq, pwkT, pwqk, ND, NS, NS, 0, 0, 0);
    sgemm128_kernel<<<dim3(NS / 128, NBT / 128, 1), 256, 0, s1>>>(tokens, pwqk, pq, NBT, NS, ND, 0, 0, 0);
    cudaEventRecord(evQK, s1);

    // main: score path
    sgemm128_kernel<<<dim3(NH / 128, NBT / 128, 1), 256>>>(tokens, w1, ph, NBT, NH, ND, 0, 0, 0);
    score_kernel<<<NBT / 8, 256>>>(w2);
    sort_kernel<<<NB, 1024>>>();
    reset_flags_kernel<<<NBT / 256, 256>>>();
    flag_ab_kernel<<<NBT / 256, 256>>>();
    flag_c_kernel<<<dim3(NT / 256, NB), 256>>>(pri);
    compact_kernel<<<NBT / 256, 256>>>();
    recompute_kernel<<<512, 256>>>(tokens, w1, w2);
    sort_kernel<<<NB, 1024>>>();
    gather_kernel<<<dim3(NP, NB), 256>>>(tokens);
    // summaries = sorted_tokens @ w_sum
    sgemm128_kernel<<<dim3(NS / 128, NB * NP / 128, 1), 256>>>(pst, w_sum, psum, NB * NP, NS, ND, 0, 0, 0);
    // pool copy (wide) + sequential per-batch update
    copy_pool_kernel<<<(NB * NP * NS / 4) / 256, 256>>>(pool);
    update_kernel<<<NB, 256>>>(pri, counts);
    // poolT = pool^T per batch
    transpose_kernel<<<dim3(NP / 32, NS / 32, NB), dim3(32, 8)>>>(ppool, ppoolT, NP, NS,
        (long long)NP * NS, (long long)NS * NP);
    // join qk chain, then attn = qk @ poolT
    cudaStreamWaitEvent(0, evQK, 0);
    sgemm128_kernel<<<dim3(NP / 128, NT / 128, NB), 256>>>(pq, ppoolT, pattn, NT, NP, NS,
        (long long)NT * NS, (long long)NS * NP, (long long)NT * NP);
    softmax_kernel<<<NBT / 8, 256>>>();
    // ap = attn @ pool ; retrieved = ap @ wv
    sgemm128_kernel<<<dim3(NS / 128, NT / 128, NB), 256>>>(pattn, ppool, pap, NT, NS, NP,
        (long long)NT * NP, (long long)NP * NS, (long long)NT * NS);
    sgemm128_kernel<<<dim3(ND / 128, NBT / 128, 1), 256>>>(pap, wv, out, NBT, ND, NS, 0, 0, 0);
    // export pool / priorities / counts
    constexpr int RET = NBT * ND;
    constexpr int REST = NB * NP * NS + NB * NP + NB;
    if (out_size >= RET + REST)
        export_kernel<<<(REST + 255) / 256, 256>>>(out + (long long)RET);
}

// round 9
// speedup vs baseline: 1.6466x; 1.0983x over previous
#include <cuda_runtime.h>
#include <math.h>

// Problem constants
constexpr int NB  = 8;
constexpr int NT  = 2048;
constexpr int ND  = 1024;
constexpr int NP  = 512;
constexpr int NS  = 256;
constexpr int NH  = 256;
constexpr int NBT = NB * NT;      // 16384

constexpr float TAUF = 1e-5f;     // at-risk flag window (fp32 pass error ~1e-6)

// ---------------- device scratch (static allocations only) ----------------
__device__ float g_h[NBT * NH];          // tokens@w1 (pre-relu)
__device__ float g_q[NBT * NS];          // qk = tokens@(wq@wk^T)
__device__ float g_scores[NBT];
__device__ int   g_order[NBT];           // per-batch sorted token indices
__device__ float g_sscores[NBT];         // per-batch sorted scores
__device__ float g_st[NB * NP * ND];     // top-512 sorted tokens
__device__ float g_sum[NB * NP * NS];    // summaries
__device__ float g_pool[NB * NP * NS];   // updated pool
__device__ float g_pri[NB * NP];
__device__ int   g_counts[NB];
__device__ float g_wkT[NS * NS];         // wk^T
__device__ float g_wqk[ND * NS];         // wq @ wk^T
__device__ float g_poolT[NB * NS * NP];  // transposed pool
__device__ float g_ap[NBT * NS];         // attn @ pool
__device__ float g_attn[NB * NT * NP];   // attention weights
__device__ int           g_flagcnt;
__device__ int           g_flaglist[NBT];
__device__ unsigned char g_flag[NBT];

// ------- 128x128x16 double-buffered SGEMM, 8x8 microtile (4+4 split) -------
// C = A(MxK) @ B(KxN), row-major; M%128==0, N%128==0, K%16==0 (all shapes here).
// Thread covers rows {ty4..+3, ty4+64..+67} x cols {tx4..+3, tx4+64..+67}:
// LDS b-reads are 16B-stride consecutive -> conflict-free.
__global__ __launch_bounds__(256, 2)
void sgemm128_kernel(const float* __restrict__ A, const float* __restrict__ Bm,
                     float* __restrict__ C, int M, int N, int K,
                     long long sA, long long sB, long long sC) {
    A  += (long long)blockIdx.z * sA;
    Bm += (long long)blockIdx.z * sB;
    C  += (long long)blockIdx.z * sC;
    __shared__ float As[2][16][128];   // k-major (transposed on store)
    __shared__ float Bs[2][16][128];

    const int tid  = threadIdx.x;
    const int row0 = blockIdx.y * 128, col0 = blockIdx.x * 128;
    // A tile load: 128 rows x 16 cols; each thread two float4
    const int ar = tid >> 1;              // 0..127
    const int ac = (tid & 1) << 3;        // 0 or 8
    // B tile load: 16 rows x 128 cols; each thread two float4
    const int br = tid >> 4;              // 0..15
    const int bc = (tid & 15) << 3;       // 0..120
    const float* Ap = A + (long long)(row0 + ar) * K + ac;
    const float* Bp = Bm + (long long)br * N + col0 + bc;
    const int tx4 = (tid & 15) << 2;      // 0..60
    const int ty4 = (tid >> 4) << 2;      // 0..60

    float acc[8][8] = {};
    float4 av0 = *(const float4*)Ap;
    float4 av1 = *(const float4*)(Ap + 4);
    float4 bv0 = *(const float4*)Bp;
    float4 bv1 = *(const float4*)(Bp + 4);
    int buf = 0;
    As[0][ac + 0][ar] = av0.x; As[0][ac + 1][ar] = av0.y;
    As[0][ac + 2][ar] = av0.z; As[0][ac + 3][ar] = av0.w;
    As[0][ac + 4][ar] = av1.x; As[0][ac + 5][ar] = av1.y;
    As[0][ac + 6][ar] = av1.z; As[0][ac + 7][ar] = av1.w;
    *(float4*)&Bs[0][br][bc]     = bv0;
    *(float4*)&Bs[0][br][bc + 4] = bv1;
    __syncthreads();

    for (int k0 = 16; k0 <= K; k0 += 16) {
        if (k0 < K) {                       // prefetch next tile into regs
            av0 = *(const float4*)(Ap + k0);
            av1 = *(const float4*)(Ap + k0 + 4);
            bv0 = *(const float4*)(Bp + (long long)k0 * N);
            bv1 = *(const float4*)(Bp + (long long)k0 * N + 4);
        }
#pragma unroll
        for (int kk = 0; kk < 16; kk++) {
            float a[8], b[8];
            *(float4*)&a[0] = *(const float4*)&As[buf][kk][ty4];
            *(float4*)&a[4] = *(const float4*)&As[buf][kk][ty4 + 64];
            *(float4*)&b[0] = *(const float4*)&Bs[buf][kk][tx4];
            *(float4*)&b[4] = *(const float4*)&Bs[buf][kk][tx4 + 64];
#pragma unroll
            for (int i = 0; i < 8; i++)
#pragma unroll
                for (int j = 0; j < 8; j++)
                    acc[i][j] = fmaf(a[i], b[j], acc[i][j]);
        }
        if (k0 < K) {
            buf ^= 1;
            As[buf][ac + 0][ar] = av0.x; As[buf][ac + 1][ar] = av0.y;
            As[buf][ac + 2][ar] = av0.z; As[buf][ac + 3][ar] = av0.w;
            As[buf][ac + 4][ar] = av1.x; As[buf][ac + 5][ar] = av1.y;
            As[buf][ac + 6][ar] = av1.z; As[buf][ac + 7][ar] = av1.w;
            *(float4*)&Bs[buf][br][bc]     = bv0;
            *(float4*)&Bs[buf][br][bc + 4] = bv1;
            __syncthreads();
        }
    }
#pragma unroll
    for (int i = 0; i < 8; i++) {
        int r = row0 + ((i < 4) ? (ty4 + i) : (ty4 + 60 + i));  // +64+(i-4)
        float* crow = C + (long long)r * N + col0;
        *(float4*)(crow + tx4)      = make_float4(acc[i][0], acc[i][1], acc[i][2], acc[i][3]);
        *(float4*)(crow + tx4 + 64) = make_float4(acc[i][4], acc[i][5], acc[i][6], acc[i][7]);
    }
}

// ---------------- scores: sigmoid(relu(h) . w2), one warp per row ----------
__global__ void score_kernel(const float* __restrict__ w2) {
    int gw = (blockIdx.x * blockDim.x + threadIdx.x) >> 5;
    int lane = threadIdx.x & 31;
    if (gw >= NBT) return;
    const float* hr = g_h + (long long)gw * NH;
    float s = 0.f;
#pragma unroll
    for (int j = 0; j < NH / 32; j++) {
        int c = lane + (j << 5);
        float v = hr[c];
        v = fmaxf(v, 0.f);
        s = fmaf(v, w2[c], s);
    }
#pragma unroll
    for (int o = 16; o; o >>= 1) s += __shfl_xor_sync(0xffffffffu, s, o);
    if (lane == 0) g_scores[gw] = 1.0f / (1.0f + expf(-s));
}

// ---------------- per-batch bitonic sort, descending score / ascending idx --
__global__ void sort_kernel() {
    __shared__ float sk[NT];
    __shared__ int   si[NT];
    int b = blockIdx.x, t = threadIdx.x;   // 1024 threads
    sk[t]        = g_scores[b * NT + t];        si[t]        = t;
    sk[t + 1024] = g_scores[b * NT + t + 1024]; si[t + 1024] = t + 1024;
    __syncthreads();
    for (int kk = 2; kk <= NT; kk <<= 1) {
        for (int j = kk >> 1; j > 0; j >>= 1) {
            for (int i = t; i < NT; i += 1024) {
                int ixj = i ^ j;
                if (ixj > i) {
                    bool ord = ((i & kk) == 0);
                    float s1 = sk[i], s2 = sk[ixj];
                    int   i1 = si[i], i2 = si[ixj];
                    bool pre = (s2 > s1) || (s2 == s1 && i2 < i1);
                    if (pre == ord) { sk[i] = s2; sk[ixj] = s1; si[i] = i2; si[ixj] = i1; }
                }
            }
            __syncthreads();
        }
    }
    g_order[b * NT + t]          = si[t];
    g_order[b * NT + t + 1024]   = si[t + 1024];
    g_sscores[b * NT + t]        = sk[t];
    g_sscores[b * NT + t + 1024] = sk[t + 1024];
}

// ---------------- at-risk flagging ----------------
__global__ void reset_flags_kernel() {
    int i = blockIdx.x * blockDim.x + threadIdx.x;
    if (i < NBT) g_flag[i] = 0;
    if (i == 0) g_flagcnt = 0;
}

__global__ void flag_ab_kernel() {
    int i = blockIdx.x * blockDim.x + threadIdx.x;   // global sorted position
    if (i >= NBT) return;
    int b = i >> 11, p = i & (NT - 1);
    float s = g_sscores[i];
    if (fabsf(s - 0.5f) < TAUF) g_flag[b * NT + g_order[i]] = 1;
    if (p + 1 < NT) {
        float s2 = g_sscores[i + 1];
        if (fabsf(s - s2) < TAUF) {
            g_flag[b * NT + g_order[i]] = 1;
            g_flag[b * NT + g_order[i + 1]] = 1;
        }
    }
}

__global__ void flag_c_kernel(const float* __restrict__ pri_in) {
    __shared__ float pr[NP];
    int b = blockIdx.y;
    for (int i = threadIdx.x; i < NP; i += blockDim.x) pr[i] = pri_in[b * NP + i];
    __syncthreads();
    int t = blockIdx.x * blockDim.x + threadIdx.x;
    if (t >= NT) return;
    float s = g_scores[b * NT + t];
    bool hit = false;
#pragma unroll 8
    for (int i = 0; i < NP; i++) hit |= (fabsf(s - pr[i]) < TAUF);
    if (hit) g_flag[b * NT + t] = 1;
}

__global__ void compact_kernel() {
    int i = blockIdx.x * blockDim.x + threadIdx.x;
    if (i < NBT && g_flag[i]) {
        int pos = atomicAdd(&g_flagcnt, 1);
        g_flaglist[pos] = i;
    }
}

// ---- double-float helpers (compensated fp32; error ~ n*eps^2 ~ 6e-14) ----
__device__ __forceinline__ void twoProd(float a, float b, float& p, float& e) {
    p = a * b;
    e = fmaf(a, b, -p);
}
__device__ __forceinline__ void twoSum(float a, float b, float& s, float& e) {
    s = a + b;
    float bb = s - a;
    e = (a - (s - bb)) + (b - bb);
}

// high-precision recompute of flagged tokens' scores on the fp32 pipe
__global__ void recompute_kernel(const float* __restrict__ tokens,
                                 const float* __restrict__ w1,
                                 const float* __restrict__ w2) {
    __shared__ double red[256];
    int j = threadIdx.x;   // 256 threads = H columns
    int n = g_flagcnt;
    if (blockIdx.x >= n) return;
    for (int li = blockIdx.x; li < n; li += gridDim.x) {
        int g = g_flaglist[li];
        const float* x = tokens + (long long)g * ND;
        const float* wcol = w1 + j;
        float hi = 0.f, lo = 0.f;
        for (int d = 0; d < ND; d++) {
            float p, pe, t;
            twoProd(x[d], wcol[(long long)d * NH], p, pe);
            twoSum(hi, p, hi, t);
            lo += t + pe;
        }
        double hd = (double)hi + (double)lo;
        float hf = fmaxf((float)hd, 0.0f);        // round to fp32, relu
        red[j] = (double)hf * (double)w2[j];
        __syncthreads();
        for (int s = 128; s; s >>= 1) {
            if (j < s) red[j] += red[j + s];
            __syncthreads();
        }
        if (j == 0) {
            double z = red[0];
            g_scores[g] = (float)(1.0 / (1.0 + exp(-z)));
        }
        __syncthreads();
    }
}

// ---------------- gather top-512 sorted tokens ----------------
__global__ void gather_kernel(const float* __restrict__ tokens) {
    int b = blockIdx.y, slot = blockIdx.x;
    int src = g_order[b * NT + slot];
    const float4* s4 = (const float4*)(tokens + ((long long)b * NT + src) * ND);
    float4* d4 = (float4*)(g_st + ((long long)b * NP + slot) * ND);
    d4[threadIdx.x] = s4[threadIdx.x];
}

// ---------------- wide pool copy (input pool -> working pool) --------------
__global__ void copy_pool_kernel(const float* __restrict__ pool_in) {
    int i = blockIdx.x * blockDim.x + threadIdx.x;   // float4 index
    ((float4*)g_pool)[i] = ((const float4*)pool_in)[i];
}

// ---- sequential pool update, deferred-write design ------------------------
// Serial phase (warp 0, pure smem): walk slots in sorted order, maintain
// priorities + two-level argmin, record lastw[dst] = last slot written there.
// Parallel phase (all 256 threads): copy summary rows once per destination.
__global__ void update_kernel(const float* __restrict__ pri_in,
                              const int* __restrict__ counts_in) {
    int b = blockIdx.x, t = threadIdx.x;   // 256 threads
    int lane = t & 31, wid = t >> 5;
    __shared__ float pri[NP];
    __shared__ float ssl[NP];
    __shared__ int   lastw[NP];
    __shared__ float gmin[16];
    __shared__ int   gidx[16];
    __shared__ int   sh_cnt;
    pri[t]         = pri_in[b * NP + t];
    pri[t + 256]   = pri_in[b * NP + t + 256];
    ssl[t]         = g_sscores[b * NT + t];
    ssl[t + 256]   = g_sscores[b * NT + t + 256];
    lastw[t]       = -1;
    lastw[t + 256] = -1;
    __syncthreads();

    if (wid == 0) {
        // init 16 group mins (first-min tie-break = lowest index)
        for (int g = 0; g < 16; g++) {
            float v = pri[(g << 5) + lane];
            int  ix = (g << 5) + lane;
#pragma unroll
            for (int o = 16; o; o >>= 1) {
                float ov = __shfl_xor_sync(0xffffffffu, v, o);
                int   oi = __shfl_xor_sync(0xffffffffu, ix, o);
                if (ov < v || (ov == v && oi < ix)) { v = ov; ix = oi; }
            }
            if (lane == 0) { gmin[g] = v; gidx[g] = ix; }
        }
        __syncwarp();
        int cnt = counts_in[b];
        for (int slot = 0; slot < NP; slot++) {
            float sc = ssl[slot];
            if (!(sc > 0.5f)) break;           // sorted descending -> done
            if (cnt < NP) {                    // insert phase
                int ins = cnt++;
                if (lane == 0) { pri[ins] = sc; lastw[ins] = slot; }
                __syncwarp();
                int g = ins >> 5;              // rescan modified group
                float v = pri[(g << 5) + lane];
                int  ix = (g << 5) + lane;
#pragma unroll
                for (int o = 16; o; o >>= 1) {
                    float ov = __shfl_xor_sync(0xffffffffu, v, o);
                    int   oi = __shfl_xor_sync(0xffffffffu, ix, o);
                    if (ov < v || (ov == v && oi < ix)) { v = ov; ix = oi; }
                }
                if (lane == 0) { gmin[g] = v; gidx[g] = ix; }
                __syncwarp();
            }
            if (cnt >= NP) {                   // replace-min (post-insert state)
                float v = (lane < 16) ? gmin[lane] : 3.4e38f;
                int  ix = (lane < 16) ? gidx[lane] : 0x7fffffff;
#pragma unroll
                for (int o = 8; o; o >>= 1) {
                    float ov = __shfl_xor_sync(0xffffffffu, v, o);
                    int   oi = __shfl_xor_sync(0xffffffffu, ix, o);
                    if (ov < v || (ov == v && oi < ix)) { v = ov; ix = oi; }
                }
                v  = __shfl_sync(0xffffffffu, v, 0);
                ix = __shfl_sync(0xffffffffu, ix, 0);
                if (sc > v) {
                    if (lane == 0) { pri[ix] = sc; lastw[ix] = slot; }
                    __syncwarp();
                    int g = ix >> 5;           // rescan modified group
                    float vv = pri[(g << 5) + lane];
                    int   ii = (g << 5) + lane;
#pragma unroll
                    for (int o = 16; o; o >>= 1) {
                        float ov = __shfl_xor_sync(0xffffffffu, vv, o);
                        int   oi = __shfl_xor_sync(0xffffffffu, ii, o);
                        if (ov < vv || (ov == vv && oi < ii)) { vv = ov; ii = oi; }
                    }
                    if (lane == 0) { gmin[g] = vv; gidx[g] = ii; }
                    __syncwarp();
                }
            }
        }
        if (lane == 0) sh_cnt = cnt;
    }
    __syncthreads();

    g_pri[b * NP + t]       = pri[t];
    g_pri[b * NP + t + 256] = pri[t + 256];
    if (t == 0) g_counts[b] = sh_cnt;

    // parallel copy phase: one warp per destination row (last writer wins,
    // already resolved in lastw)
    float*       poolb = g_pool + (long long)b * NP * NS;
    const float* summb = g_sum + (long long)b * NP * NS;
    for (int d = wid; d < NP; d += 8) {
        int s = lastw[d];
        if (s >= 0) {
            const float4* srcr = (const float4*)(summb + (long long)s * NS);
            float4*       dstr = (float4*)(poolb + (long long)d * NS);
            dstr[lane]      = srcr[lane];
            dstr[lane + 32] = srcr[lane + 32];
        }
    }
}

// ---------------- generic batched transpose: src[R,C] -> dst[C,R] ----------
__global__ void transpose_kernel(const float* __restrict__ src, float* __restrict__ dst,
                                 int R, int C, long long sS, long long sD) {
    __shared__ float tile[32][33];
    src += (long long)blockIdx.z * sS;
    dst += (long long)blockIdx.z * sD;
    int r0 = blockIdx.x * 32, c0 = blockIdx.y * 32;
    int x = threadIdx.x, y = threadIdx.y;   // 32 x 8
#pragma unroll
    for (int i = 0; i < 32; i += 8)
        tile[y + i][x] = src[(long long)(r0 + y + i) * C + c0 + x];
    __syncthreads();
#pragma unroll
    for (int i = 0; i < 32; i += 8)
        dst[(long long)(c0 + y + i) * R + r0 + x] = tile[x][y + i];
}

// ---------------- masked softmax over attn rows (warp per row) -------------
__global__ void softmax_kernel() {
    int gw = (blockIdx.x * blockDim.x + threadIdx.x) >> 5;
    int lane = threadIdx.x & 31;
    if (gw >= NBT) return;
    int b = gw >> 11;
    int cnt = g_counts[b];
    float* row = g_attn + (long long)gw * NP;
    float vals[NP / 32];
    float m = -1e30f;
#pragma unroll
    for (int j = 0; j < NP / 32; j++) {
        int p = lane + (j << 5);
        float v = row[p] * 0.0625f;   // 1/sqrt(256)
        vals[j] = v;
        if (p < cnt) m = fmaxf(m, v);
    }
#pragma unroll
    for (int o = 16; o; o >>= 1) m = fmaxf(m, __shfl_xor_sync(0xffffffffu, m, o));
    float s = 0.f;
#pragma unroll
    for (int j = 0; j < NP / 32; j++) {
        int p = lane + (j << 5);
        float e = (p < cnt) ? expf(vals[j] - m) : 0.f;
        vals[j] = e;
        s += e;
    }
#pragma unroll
    for (int o = 16; o; o >>= 1) s += __shfl_xor_sync(0xffffffffu, s, o);
    float inv = (cnt > 0) ? 1.f / s : 0.f;
#pragma unroll
    for (int j = 0; j < NP / 32; j++) row[lane + (j << 5)] = vals[j] * inv;
}

// ---------------- export pool / priorities / counts into d_out -------------
__global__ void export_kernel(float* __restrict__ dst) {
    int i = blockIdx.x * blockDim.x + threadIdx.x;
    constexpr int PS = NB * NP * NS;
    if (i < PS) dst[i] = g_pool[i];
    else if (i < PS + NB * NP) dst[i] = g_pri[i - PS];
    else if (i < PS + NB * NP + NB) dst[i] = (float)g_counts[i - PS - NB * NP];
}

// ---------------- launch ----------------
extern "C" void kernel_launch(void* const* d_in, const int* in_sizes, int n_in,
                              void* d_out, int out_size) {
    const float* tokens = (const float*)d_in[0];
    const float* pool   = (const float*)d_in[1];
    const float* pri    = (const float*)d_in[2];
    const int*   counts = (const int*)d_in[3];
    const float* w1     = (const float*)d_in[4];
    const float* w2     = (const float*)d_in[5];
    const float* w_sum  = (const float*)d_in[6];
    const float* wq     = (const float*)d_in[7];
    const float* wk     = (const float*)d_in[8];
    const float* wv     = (const float*)d_in[9];
    float* out = (float*)d_out;
    (void)in_sizes; (void)n_in;

    float *ph, *pq, *pst, *psum, *ppool, *pwkT, *pwqk, *ppoolT, *pap, *pattn;
    cudaGetSymbolAddress((void**)&ph,     g_h);
    cudaGetSymbolAddress((void**)&pq,     g_q);
    cudaGetSymbolAddress((void**)&pst,    g_st);
    cudaGetSymbolAddress((void**)&psum,   g_sum);
    cudaGetSymbolAddress((void**)&ppool,  g_pool);
    cudaGetSymbolAddress((void**)&pwkT,   g_wkT);
    cudaGetSymbolAddress((void**)&pwqk,   g_wqk);
    cudaGetSymbolAddress((void**)&ppoolT, g_poolT);
    cudaGetSymbolAddress((void**)&pap,    g_ap);
    cudaGetSymbolAddress((void**)&pattn,  g_attn);

    // side stream for the independent qk chain
    cudaStream_t s1;
    cudaStreamCreateWithFlags(&s1, cudaStreamNonBlocking);
    cudaEvent_t evFork, evQK;
    cudaEventCreateWithFlags(&evFork, cudaEventDisableTiming);
    cudaEventCreateWithFlags(&evQK, cudaEventDisableTiming);

    cudaEventRecord(evFork, 0);
    cudaStreamWaitEvent(s1, evFork, 0);
    // s1: wkT = wk^T; wqk = wq @ wkT; qk = tokens @ wqk
    transpose_kernel<<<dim3(NS / 32, NS / 32, 1), dim3(32, 8), 0, s1>>>(wk, pwkT, NS, NS, 0, 0);
    sgemm128_kernel<<<dim3(NS / 128, ND / 128, 1), 256, 0, s1>>>(wq, pwkT, pwqk, ND, NS, NS, 0, 0, 0);
    sgemm128_kernel<<<dim3(NS / 128, NBT / 128, 1), 256, 0, s1>>>(tokens, pwqk, pq, NBT, NS, ND, 0, 0, 0);
    cudaEventRecord(evQK, s1);

    // main: score path
    sgemm128_kernel<<<dim3(NH / 128, NBT / 128, 1), 256>>>(tokens, w1, ph, NBT, NH, ND, 0, 0, 0);
    score_kernel<<<NBT / 8, 256>>>(w2);
    sort_kernel<<<NB, 1024>>>();
    reset_flags_kernel<<<NBT / 256, 256>>>();
    flag_ab_kernel<<<NBT / 256, 256>>>();
    flag_c_kernel<<<dim3(NT / 256, NB), 256>>>(pri);
    compact_kernel<<<NBT / 256, 256>>>();
    recompute_kernel<<<512, 256>>>(tokens, w1, w2);
    sort_kernel<<<NB, 1024>>>();
    gather_kernel<<<dim3(NP, NB), 256>>>(tokens);
    // summaries = sorted_tokens @ w_sum
    sgemm128_kernel<<<dim3(NS / 128, NB * NP / 128, 1), 256>>>(pst, w_sum, psum, NB * NP, NS, ND, 0, 0, 0);
    // pool copy (wide) + sequential per-batch update (deferred-write)
    copy_pool_kernel<<<(NB * NP * NS / 4) / 256, 256>>>(pool);
    update_kernel<<<NB, 256>>>(pri, counts);
    // poolT = pool^T per batch
    transpose_kernel<<<dim3(NP / 32, NS / 32, NB), dim3(32, 8)>>>(ppool, ppoolT, NP, NS,
        (long long)NP * NS, (long long)NS * NP);
    // join qk chain, then attn = qk @ poolT
    cudaStreamWaitEvent(0, evQK, 0);
    sgemm128_kernel<<<dim3(NP / 128, NT / 128, NB), 256>>>(pq, ppoolT, pattn, NT, NP, NS,
        (long long)NT * NS, (long long)NS * NP, (long long)NT * NP);
    softmax_kernel<<<NBT / 8, 256>>>();
    // ap = attn @ pool ; retrieved = ap @ wv
    sgemm128_kernel<<<dim3(NS / 128, NT / 128, NB), 256>>>(pattn, ppool, pap, NT, NS, NP,
        (long long)NT * NP, (long long)NP * NS, (long long)NT * NS);
    sgemm128_kernel<<<dim3(ND / 128, NBT / 128, 1), 256>>>(pap, wv, out, NBT, ND, NS, 0, 0, 0);
    // export pool / priorities / counts
    constexpr int RET = NBT * ND;
    constexpr int REST = NB * NP * NS + NB * NP + NB;
    if (out_size >= RET + REST)
        export_kernel<<<(REST + 255) / 256, 256>>>(out + (long long)RET);
}

// round 10
// speedup vs baseline: 1.7682x; 1.0738x over previous
#include <cuda_runtime.h>
#include <math.h>

// Problem constants
constexpr int NB  = 8;
constexpr int NT  = 2048;
constexpr int ND  = 1024;
constexpr int NP  = 512;
constexpr int NS  = 256;
constexpr int NH  = 256;
constexpr int NBT = NB * NT;      // 16384

constexpr float TAUF = 1e-5f;     // at-risk flag window (fp32 pass error ~1e-6)

// ---------------- device scratch (static allocations only) ----------------
__device__ float g_h[NBT * NH];          // tokens@w1 (pre-relu)
__device__ float g_q[NBT * NS];          // qk = tokens@(wq@wk^T)
__device__ float g_scores[NBT];
__device__ int   g_order[NBT];           // per-batch sorted token indices
__device__ float g_sscores[NBT];         // per-batch sorted scores
__device__ float g_st[NB * NP * ND];     // top-512 sorted tokens
__device__ float g_sum[NB * NP * NS];    // summaries
__device__ float g_pool[NB * NP * NS];   // updated pool
__device__ float g_pri[NB * NP];
__device__ int   g_counts[NB];
__device__ float g_wkT[NS * NS];         // wk^T
__device__ float g_wqk[ND * NS];         // wq @ wk^T
__device__ float g_poolT[NB * NS * NP];  // transposed pool
__device__ float g_ap[NBT * NS];         // attn @ pool
__device__ float g_attn[NB * NT * NP];   // attention weights
__device__ int           g_flagcnt;
__device__ int           g_flaglist[NBT];
__device__ unsigned char g_flag[NBT];

// ------- 128x128x16 double-buffered SGEMM, 8x8 microtile (4+4 split) -------
// Register-pipelined fragment loads: load kk+1 while computing kk.
__global__ __launch_bounds__(256, 2)
void sgemm128_kernel(const float* __restrict__ A, const float* __restrict__ Bm,
                     float* __restrict__ C, int M, int N, int K,
                     long long sA, long long sB, long long sC) {
    A  += (long long)blockIdx.z * sA;
    Bm += (long long)blockIdx.z * sB;
    C  += (long long)blockIdx.z * sC;
    __shared__ float As[2][16][128];   // k-major (transposed on store)
    __shared__ float Bs[2][16][128];

    const int tid  = threadIdx.x;
    const int row0 = blockIdx.y * 128, col0 = blockIdx.x * 128;
    const int ar = tid >> 1;              // 0..127
    const int ac = (tid & 1) << 3;        // 0 or 8
    const int br = tid >> 4;              // 0..15
    const int bc = (tid & 15) << 3;       // 0..120
    const float* Ap = A + (long long)(row0 + ar) * K + ac;
    const float* Bp = Bm + (long long)br * N + col0 + bc;
    const int tx4 = (tid & 15) << 2;      // 0..60
    const int ty4 = (tid >> 4) << 2;      // 0..60

    float acc[8][8] = {};
    float af[2][8], bf[2][8];
    float4 av0 = *(const float4*)Ap;
    float4 av1 = *(const float4*)(Ap + 4);
    float4 bv0 = *(const float4*)Bp;
    float4 bv1 = *(const float4*)(Bp + 4);
    int buf = 0;
    As[0][ac + 0][ar] = av0.x; As[0][ac + 1][ar] = av0.y;
    As[0][ac + 2][ar] = av0.z; As[0][ac + 3][ar] = av0.w;
    As[0][ac + 4][ar] = av1.x; As[0][ac + 5][ar] = av1.y;
    As[0][ac + 6][ar] = av1.z; As[0][ac + 7][ar] = av1.w;
    *(float4*)&Bs[0][br][bc]     = bv0;
    *(float4*)&Bs[0][br][bc + 4] = bv1;
    __syncthreads();
    *(float4*)&af[0][0] = *(const float4*)&As[0][0][ty4];
    *(float4*)&af[0][4] = *(const float4*)&As[0][0][ty4 + 64];
    *(float4*)&bf[0][0] = *(const float4*)&Bs[0][0][tx4];
    *(float4*)&bf[0][4] = *(const float4*)&Bs[0][0][tx4 + 64];

    for (int k0 = 16; k0 <= K; k0 += 16) {
        if (k0 < K) {                       // prefetch next tile into regs
            av0 = *(const float4*)(Ap + k0);
            av1 = *(const float4*)(Ap + k0 + 4);
            bv0 = *(const float4*)(Bp + (long long)k0 * N);
            bv1 = *(const float4*)(Bp + (long long)k0 * N + 4);
        }
#pragma unroll
        for (int kk = 0; kk < 16; kk++) {
            const int cur = kk & 1;
            if (kk < 15) {                  // pipeline: load kk+1 fragments
                const int nxt = cur ^ 1;
                *(float4*)&af[nxt][0] = *(const float4*)&As[buf][kk + 1][ty4];
                *(float4*)&af[nxt][4] = *(const float4*)&As[buf][kk + 1][ty4 + 64];
                *(float4*)&bf[nxt][0] = *(const float4*)&Bs[buf][kk + 1][tx4];
                *(float4*)&bf[nxt][4] = *(const float4*)&Bs[buf][kk + 1][tx4 + 64];
            }
#pragma unroll
            for (int i = 0; i < 8; i++)
#pragma unroll
                for (int j = 0; j < 8; j++)
                    acc[i][j] = fmaf(af[cur][i], bf[cur][j], acc[i][j]);
        }
        if (k0 < K) {
            buf ^= 1;
            As[buf][ac + 0][ar] = av0.x; As[buf][ac + 1][ar] = av0.y;
            As[buf][ac + 2][ar] = av0.z; As[buf][ac + 3][ar] = av0.w;
            As[buf][ac + 4][ar] = av1.x; As[buf][ac + 5][ar] = av1.y;
            As[buf][ac + 6][ar] = av1.z; As[buf][ac + 7][ar] = av1.w;
            *(float4*)&Bs[buf][br][bc]     = bv0;
            *(float4*)&Bs[buf][br][bc + 4] = bv1;
            __syncthreads();
            *(float4*)&af[0][0] = *(const float4*)&As[buf][0][ty4];
            *(float4*)&af[0][4] = *(const float4*)&As[buf][0][ty4 + 64];
            *(float4*)&bf[0][0] = *(const float4*)&Bs[buf][0][tx4];
            *(float4*)&bf[0][4] = *(const float4*)&Bs[buf][0][tx4 + 64];
        }
    }
#pragma unroll
    for (int i = 0; i < 8; i++) {
        int r = row0 + ((i < 4) ? (ty4 + i) : (ty4 + 60 + i));  // +64+(i-4)
        float* crow = C + (long long)r * N + col0;
        *(float4*)(crow + tx4)      = make_float4(acc[i][0], acc[i][1], acc[i][2], acc[i][3]);
        *(float4*)(crow + tx4 + 64) = make_float4(acc[i][4], acc[i][5], acc[i][6], acc[i][7]);
    }
}

// ------- 64x128x16 variant (4x8 microtile) for small-M GEMMs ---------------
// Doubles the grid for M=4096/N=256 shapes so the whole chip is busy.
__global__ __launch_bounds__(256, 2)
void sgemm64_kernel(const float* __restrict__ A, const float* __restrict__ Bm,
                    float* __restrict__ C, int M, int N, int K,
                    long long sA, long long sB, long long sC) {
    A  += (long long)blockIdx.z * sA;
    Bm += (long long)blockIdx.z * sB;
    C  += (long long)blockIdx.z * sC;
    __shared__ float As[2][16][64];    // k-major
    __shared__ float Bs[2][16][128];

    const int tid  = threadIdx.x;
    const int row0 = blockIdx.y * 64, col0 = blockIdx.x * 128;
    // A tile: 64 rows x 16 cols; one float4 per thread
    const int ar = tid >> 2;              // 0..63
    const int ac = (tid & 3) << 2;        // 0,4,8,12
    // B tile: 16 rows x 128 cols; two float4 per thread
    const int br = tid >> 4;              // 0..15
    const int bc = (tid & 15) << 3;       // 0..120
    const float* Ap = A + (long long)(row0 + ar) * K + ac;
    const float* Bp = Bm + (long long)br * N + col0 + bc;
    const int tx4 = (tid & 15) << 2;      // 0..60
    const int ty4 = (tid >> 4) << 2;      // 0..60

    float acc[4][8] = {};
    float af[2][4], bf[2][8];
    float4 av = *(const float4*)Ap;
    float4 bv0 = *(const float4*)Bp;
    float4 bv1 = *(const float4*)(Bp + 4);
    int buf = 0;
    As[0][ac + 0][ar] = av.x; As[0][ac + 1][ar] = av.y;
    As[0][ac + 2][ar] = av.z; As[0][ac + 3][ar] = av.w;
    *(float4*)&Bs[0][br][bc]     = bv0;
    *(float4*)&Bs[0][br][bc + 4] = bv1;
    __syncthreads();
    *(float4*)&af[0][0] = *(const float4*)&As[0][0][ty4];
    *(float4*)&bf[0][0] = *(const float4*)&Bs[0][0][tx4];
    *(float4*)&bf[0][4] = *(const float4*)&Bs[0][0][tx4 + 64];

    for (int k0 = 16; k0 <= K; k0 += 16) {
        if (k0 < K) {
            av  = *(const float4*)(Ap + k0);
            bv0 = *(const float4*)(Bp + (long long)k0 * N);
            bv1 = *(const float4*)(Bp + (long long)k0 * N + 4);
        }
#pragma unroll
        for (int kk = 0; kk < 16; kk++) {
            const int cur = kk & 1;
            if (kk < 15) {
                const int nxt = cur ^ 1;
                *(float4*)&af[nxt][0] = *(const float4*)&As[buf][kk + 1][ty4];
                *(float4*)&bf[nxt][0] = *(const float4*)&Bs[buf][kk + 1][tx4];
                *(float4*)&bf[nxt][4] = *(const float4*)&Bs[buf][kk + 1][tx4 + 64];
            }
#pragma unroll
            for (int i = 0; i < 4; i++)
#pragma unroll
                for (int j = 0; j < 8; j++)
                    acc[i][j] = fmaf(af[cur][i], bf[cur][j], acc[i][j]);
        }
        if (k0 < K) {
            buf ^= 1;
            As[buf][ac + 0][ar] = av.x; As[buf][ac + 1][ar] = av.y;
            As[buf][ac + 2][ar] = av.z; As[buf][ac + 3][ar] = av.w;
            *(float4*)&Bs[buf][br][bc]     = bv0;
            *(float4*)&Bs[buf][br][bc + 4] = bv1;
            __syncthreads();
            *(float4*)&af[0][0] = *(const float4*)&As[buf][0][ty4];
            *(float4*)&bf[0][0] = *(const float4*)&Bs[buf][0][tx4];
            *(float4*)&bf[0][4] = *(const float4*)&Bs[buf][0][tx4 + 64];
        }
    }
#pragma unroll
    for (int i = 0; i < 4; i++) {
        float* crow = C + (long long)(row0 + ty4 + i) * N + col0;
        *(float4*)(crow + tx4)      = make_float4(acc[i][0], acc[i][1], acc[i][2], acc[i][3]);
        *(float4*)(crow + tx4 + 64) = make_float4(acc[i][4], acc[i][5], acc[i][6], acc[i][7]);
    }
}

// ---------------- scores: sigmoid(relu(h) . w2), one warp per row ----------
__global__ void score_kernel(const float* __restrict__ w2) {
    int gw = (blockIdx.x * blockDim.x + threadIdx.x) >> 5;
    int lane = threadIdx.x & 31;
    if (gw >= NBT) return;
    const float* hr = g_h + (long long)gw * NH;
    float s = 0.f;
#pragma unroll
    for (int j = 0; j < NH / 32; j++) {
        int c = lane + (j << 5);
        float v = hr[c];
        v = fmaxf(v, 0.f);
        s = fmaf(v, w2[c], s);
    }
#pragma unroll
    for (int o = 16; o; o >>= 1) s += __shfl_xor_sync(0xffffffffu, s, o);
    if (lane == 0) g_scores[gw] = 1.0f / (1.0f + expf(-s));
}

// ---------------- per-batch bitonic sort, descending score / ascending idx --
__global__ void sort_kernel() {
    __shared__ float sk[NT];
    __shared__ int   si[NT];
    int b = blockIdx.x, t = threadIdx.x;   // 1024 threads
    sk[t]        = g_scores[b * NT + t];        si[t]        = t;
    sk[t + 1024] = g_scores[b * NT + t + 1024]; si[t + 1024] = t + 1024;
    __syncthreads();
    for (int kk = 2; kk <= NT; kk <<= 1) {
        for (int j = kk >> 1; j > 0; j >>= 1) {
            for (int i = t; i < NT; i += 1024) {
                int ixj = i ^ j;
                if (ixj > i) {
                    bool ord = ((i & kk) == 0);
                    float s1 = sk[i], s2 = sk[ixj];
                    int   i1 = si[i], i2 = si[ixj];
                    bool pre = (s2 > s1) || (s2 == s1 && i2 < i1);
                    if (pre == ord) { sk[i] = s2; sk[ixj] = s1; si[i] = i2; si[ixj] = i1; }
                }
            }
            __syncthreads();
        }
    }
    g_order[b * NT + t]          = si[t];
    g_order[b * NT + t + 1024]   = si[t + 1024];
    g_sscores[b * NT + t]        = sk[t];
    g_sscores[b * NT + t + 1024] = sk[t + 1024];
}

// ---------------- at-risk flagging ----------------
__global__ void reset_flags_kernel() {
    int i = blockIdx.x * blockDim.x + threadIdx.x;
    if (i < NBT) g_flag[i] = 0;
    if (i == 0) g_flagcnt = 0;
}

__global__ void flag_ab_kernel() {
    int i = blockIdx.x * blockDim.x + threadIdx.x;   // global sorted position
    if (i >= NBT) return;
    int b = i >> 11, p = i & (NT - 1);
    float s = g_sscores[i];
    if (fabsf(s - 0.5f) < TAUF) g_flag[b * NT + g_order[i]] = 1;
    if (p + 1 < NT) {
        float s2 = g_sscores[i + 1];
        if (fabsf(s - s2) < TAUF) {
            g_flag[b * NT + g_order[i]] = 1;
            g_flag[b * NT + g_order[i + 1]] = 1;
        }
    }
}

__global__ void flag_c_kernel(const float* __restrict__ pri_in) {
    __shared__ float pr[NP];
    int b = blockIdx.y;
    for (int i = threadIdx.x; i < NP; i += blockDim.x) pr[i] = pri_in[b * NP + i];
    __syncthreads();
    int t = blockIdx.x * blockDim.x + threadIdx.x;
    if (t >= NT) return;
    float s = g_scores[b * NT + t];
    bool hit = false;
#pragma unroll 8
    for (int i = 0; i < NP; i++) hit |= (fabsf(s - pr[i]) < TAUF);
    if (hit) g_flag[b * NT + t] = 1;
}

__global__ void compact_kernel() {
    int i = blockIdx.x * blockDim.x + threadIdx.x;
    if (i < NBT && g_flag[i]) {
        int pos = atomicAdd(&g_flagcnt, 1);
        g_flaglist[pos] = i;
    }
}

// ---- double-float helpers (compensated fp32; error ~ n*eps^2 ~ 6e-14) ----
__device__ __forceinline__ void twoProd(float a, float b, float& p, float& e) {
    p = a * b;
    e = fmaf(a, b, -p);
}
__device__ __forceinline__ void twoSum(float a, float b, float& s, float& e) {
    s = a + b;
    float bb = s - a;
    e = (a - (s - bb)) + (b - bb);
}

// high-precision recompute of flagged tokens' scores on the fp32 pipe
__global__ void recompute_kernel(const float* __restrict__ tokens,
                                 const float* __restrict__ w1,
                                 const float* __restrict__ w2) {
    __shared__ double red[256];
    int j = threadIdx.x;   // 256 threads = H columns
    int n = g_flagcnt;
    if (blockIdx.x >= n) return;
    for (int li = blockIdx.x; li < n; li += gridDim.x) {
        int g = g_flaglist[li];
        const float* x = tokens + (long long)g * ND;
        const float* wcol = w1 + j;
        float hi = 0.f, lo = 0.f;
        for (int d = 0; d < ND; d++) {
            float p, pe, t;
            twoProd(x[d], wcol[(long long)d * NH], p, pe);
            twoSum(hi, p, hi, t);
            lo += t + pe;
        }
        double hd = (double)hi + (double)lo;
        float hf = fmaxf((float)hd, 0.0f);        // round to fp32, relu
        red[j] = (double)hf * (double)w2[j];
        __syncthreads();
        for (int s = 128; s; s >>= 1) {
            if (j < s) red[j] += red[j + s];
            __syncthreads();
        }
        if (j == 0) {
            double z = red[0];
            g_scores[g] = (float)(1.0 / (1.0 + exp(-z)));
        }
        __syncthreads();
    }
}

// ---------------- gather top-512 sorted tokens ----------------
__global__ void gather_kernel(const float* __restrict__ tokens) {
    int b = blockIdx.y, slot = blockIdx.x;
    int src = g_order[b * NT + slot];
    const float4* s4 = (const float4*)(tokens + ((long long)b * NT + src) * ND);
    float4* d4 = (float4*)(g_st + ((long long)b * NP + slot) * ND);
    d4[threadIdx.x] = s4[threadIdx.x];
}

// ---------------- wide pool copy (input pool -> working pool) --------------
__global__ void copy_pool_kernel(const float* __restrict__ pool_in) {
    int i = blockIdx.x * blockDim.x + threadIdx.x;   // float4 index
    ((float4*)g_pool)[i] = ((const float4*)pool_in)[i];
}

// ---- sequential pool update, deferred-write design ------------------------
__global__ void update_kernel(const float* __restrict__ pri_in,
                              const int* __restrict__ counts_in) {
    int b = blockIdx.x, t = threadIdx.x;   // 256 threads
    int lane = t & 31, wid = t >> 5;
    __shared__ float pri[NP];
    __shared__ float ssl[NP];
    __shared__ int   lastw[NP];
    __shared__ float gmin[16];
    __shared__ int   gidx[16];
    __shared__ int   sh_cnt;
    pri[t]         = pri_in[b * NP + t];
    pri[t + 256]   = pri_in[b * NP + t + 256];
    ssl[t]         = g_sscores[b * NT + t];
    ssl[t + 256]   = g_sscores[b * NT + t + 256];
    lastw[t]       = -1;
    lastw[t + 256] = -1;
    __syncthreads();

    if (wid == 0) {
        for (int g = 0; g < 16; g++) {
            float v = pri[(g << 5) + lane];
            int  ix = (g << 5) + lane;
#pragma unroll
            for (int o = 16; o; o >>= 1) {
                float ov = __shfl_xor_sync(0xffffffffu, v, o);
                int   oi = __shfl_xor_sync(0xffffffffu, ix, o);
                if (ov < v || (ov == v && oi < ix)) { v = ov; ix = oi; }
            }
            if (lane == 0) { gmin[g] = v; gidx[g] = ix; }
        }
        __syncwarp();
        int cnt = counts_in[b];
        for (int slot = 0; slot < NP; slot++) {
            float sc = ssl[slot];
            if (!(sc > 0.5f)) break;           // sorted descending -> done
            if (cnt < NP) {                    // insert phase
                int ins = cnt++;
                if (lane == 0) { pri[ins] = sc; lastw[ins] = slot; }
                __syncwarp();
                int g = ins >> 5;              // rescan modified group
                float v = pri[(g << 5) + lane];
                int  ix = (g << 5) + lane;
#pragma unroll
                for (int o = 16; o; o >>= 1) {
                    float ov = __shfl_xor_sync(0xffffffffu, v, o);
                    int   oi = __shfl_xor_sync(0xffffffffu, ix, o);
                    if (ov < v || (ov == v && oi < ix)) { v = ov; ix = oi; }
                }
                if (lane == 0) { gmin[g] = v; gidx[g] = ix; }
                __syncwarp();
            }
            if (cnt >= NP) {                   // replace-min (post-insert state)
                float v = (lane < 16) ? gmin[lane] : 3.4e38f;
                int  ix = (lane < 16) ? gidx[lane] : 0x7fffffff;
#pragma unroll
                for (int o = 8; o; o >>= 1) {
                    float ov = __shfl_xor_sync(0xffffffffu, v, o);
                    int   oi = __shfl_xor_sync(0xffffffffu, ix, o);
                    if (ov < v || (ov == v && oi < ix)) { v = ov; ix = oi; }
                }
                v  = __shfl_sync(0xffffffffu, v, 0);
                ix = __shfl_sync(0xffffffffu, ix, 0);
                if (sc > v) {
                    if (lane == 0) { pri[ix] = sc; lastw[ix] = slot; }
                    __syncwarp();
                    int g = ix >> 5;           // rescan modified group
                    float vv = pri[(g << 5) + lane];
                    int   ii = (g << 5) + lane;
#pragma unroll
                    for (int o = 16; o; o >>= 1) {
                        float ov = __shfl_xor_sync(0xffffffffu, vv, o);
                        int   oi = __shfl_xor_sync(0xffffffffu, ii, o);
                        if (ov < vv || (ov == vv && oi < ii)) { vv = ov; ii = oi; }
                    }
                    if (lane == 0) { gmin[g] = vv; gidx[g] = ii; }
                    __syncwarp();
                }
            }
        }
        if (lane == 0) sh_cnt = cnt;
    }
    __syncthreads();

    g_pri[b * NP + t]       = pri[t];
    g_pri[b * NP + t + 256] = pri[t + 256];
    if (t == 0) g_counts[b] = sh_cnt;

    // parallel copy phase: one warp per destination row (last writer wins)
    float*       poolb = g_pool + (long long)b * NP * NS;
    const float* summb = g_sum + (long long)b * NP * NS;
    for (int d = wid; d < NP; d += 8) {
        int s = lastw[d];
        if (s >= 0) {
            const float4* srcr = (const float4*)(summb + (long long)s * NS);
            float4*       dstr = (float4*)(poolb + (long long)d * NS);
            dstr[lane]      = srcr[lane];
            dstr[lane + 32] = srcr[lane + 32];
        }
    }
}

// ---------------- generic batched transpose: src[R,C] -> dst[C,R] ----------
__global__ void transpose_kernel(const float* __restrict__ src, float* __restrict__ dst,
                                 int R, int C, long long sS, long long sD) {
    __shared__ float tile[32][33];
    src += (long long)blockIdx.z * sS;
    dst += (long long)blockIdx.z * sD;
    int r0 = blockIdx.x * 32, c0 = blockIdx.y * 32;
    int x = threadIdx.x, y = threadIdx.y;   // 32 x 8
#pragma unroll
    for (int i = 0; i < 32; i += 8)
        tile[y + i][x] = src[(long long)(r0 + y + i) * C + c0 + x];
    __syncthreads();
#pragma unroll
    for (int i = 0; i < 32; i += 8)
        dst[(long long)(c0 + y + i) * R + r0 + x] = tile[x][y + i];
}

// ---------------- masked softmax over attn rows (warp per row) -------------
__global__ void softmax_kernel() {
    int gw = (blockIdx.x * blockDim.x + threadIdx.x) >> 5;
    int lane = threadIdx.x & 31;
    if (gw >= NBT) return;
    int b = gw >> 11;
    int cnt = g_counts[b];
    float* row = g_attn + (long long)gw * NP;
    float vals[NP / 32];
    float m = -1e30f;
#pragma unroll
    for (int j = 0; j < NP / 32; j++) {
        int p = lane + (j << 5);
        float v = row[p] * 0.0625f;   // 1/sqrt(256)
        vals[j] = v;
        if (p < cnt) m = fmaxf(m, v);
    }
#pragma unroll
    for (int o = 16; o; o >>= 1) m = fmaxf(m, __shfl_xor_sync(0xffffffffu, m, o));
    float s = 0.f;
#pragma unroll
    for (int j = 0; j < NP / 32; j++) {
        int p = lane + (j << 5);
        float e = (p < cnt) ? expf(vals[j] - m) : 0.f;
        vals[j] = e;
        s += e;
    }
#pragma unroll
    for (int o = 16; o; o >>= 1) s += __shfl_xor_sync(0xffffffffu, s, o);
    float inv = (cnt > 0) ? 1.f / s : 0.f;
#pragma unroll
    for (int j = 0; j < NP / 32; j++) row[lane + (j << 5)] = vals[j] * inv;
}

// ---------------- export pool / priorities / counts into d_out -------------
__global__ void export_kernel(float* __restrict__ dst) {
    int i = blockIdx.x * blockDim.x + threadIdx.x;
    constexpr int PS = NB * NP * NS;
    if (i < PS) dst[i] = g_pool[i];
    else if (i < PS + NB * NP) dst[i] = g_pri[i - PS];
    else if (i < PS + NB * NP + NB) dst[i] = (float)g_counts[i - PS - NB * NP];
}

// ---------------- launch ----------------
extern "C" void kernel_launch(void* const* d_in, const int* in_sizes, int n_in,
                              void* d_out, int out_size) {
    const float* tokens = (const float*)d_in[0];
    const float* pool   = (const float*)d_in[1];
    const float* pri    = (const float*)d_in[2];
    const int*   counts = (const int*)d_in[3];
    const float* w1     = (const float*)d_in[4];
    const float* w2     = (const float*)d_in[5];
    const float* w_sum  = (const float*)d_in[6];
    const float* wq     = (const float*)d_in[7];
    const float* wk     = (const float*)d_in[8];
    const float* wv     = (const float*)d_in[9];
    float* out = (float*)d_out;
    (void)in_sizes; (void)n_in;

    float *ph, *pq, *pst, *psum, *ppool, *pwkT, *pwqk, *ppoolT, *pap, *pattn;
    cudaGetSymbolAddress((void**)&ph,     g_h);
    cudaGetSymbolAddress((void**)&pq,     g_q);
    cudaGetSymbolAddress((void**)&pst,    g_st);
    cudaGetSymbolAddress((void**)&psum,   g_sum);
    cudaGetSymbolAddress((void**)&ppool,  g_pool);
    cudaGetSymbolAddress((void**)&pwkT,   g_wkT);
    cudaGetSymbolAddress((void**)&pwqk,   g_wqk);
    cudaGetSymbolAddress((void**)&ppoolT, g_poolT);
    cudaGetSymbolAddress((void**)&pap,    g_ap);
    cudaGetSymbolAddress((void**)&pattn,  g_attn);

    // side stream for the independent qk chain + export tail
    cudaStream_t s1;
    cudaStreamCreateWithFlags(&s1, cudaStreamNonBlocking);
    cudaEvent_t evFork, evQK, evUPD;
    cudaEventCreateWithFlags(&evFork, cudaEventDisableTiming);
    cudaEventCreateWithFlags(&evQK, cudaEventDisableTiming);
    cudaEventCreateWithFlags(&evUPD, cudaEventDisableTiming);

    cudaEventRecord(evFork, 0);
    cudaStreamWaitEvent(s1, evFork, 0);
    // s1: wkT = wk^T; wqk = wq @ wkT; qk = tokens @ wqk
    transpose_kernel<<<dim3(NS / 32, NS / 32, 1), dim3(32, 8), 0, s1>>>(wk, pwkT, NS, NS, 0, 0);
    sgemm128_kernel<<<dim3(NS / 128, ND / 128, 1), 256, 0, s1>>>(wq, pwkT, pwqk, ND, NS, NS, 0, 0, 0);
    sgemm128_kernel<<<dim3(NS / 128, NBT / 128, 1), 256, 0, s1>>>(tokens, pwqk, pq, NBT, NS, ND, 0, 0, 0);
    cudaEventRecord(evQK, s1);

    // main: score path
    sgemm128_kernel<<<dim3(NH / 128, NBT / 128, 1), 256>>>(tokens, w1, ph, NBT, NH, ND, 0, 0, 0);
    score_kernel<<<NBT / 8, 256>>>(w2);
    sort_kernel<<<NB, 1024>>>();
    reset_flags_kernel<<<NBT / 256, 256>>>();
    flag_ab_kernel<<<NBT / 256, 256>>>();
    flag_c_kernel<<<dim3(NT / 256, NB), 256>>>(pri);
    compact_kernel<<<NBT / 256, 256>>>();
    recompute_kernel<<<512, 256>>>(tokens, w1, w2);
    sort_kernel<<<NB, 1024>>>();
    gather_kernel<<<dim3(NP, NB), 256>>>(tokens);
    // summaries = sorted_tokens @ w_sum  (64-row tiles -> 128 blocks)
    sgemm64_kernel<<<dim3(NS / 128, NB * NP / 64, 1), 256>>>(pst, w_sum, psum, NB * NP, NS, ND, 0, 0, 0);
    // pool copy (wide) + sequential per-batch update (deferred-write)
    copy_pool_kernel<<<(NB * NP * NS / 4) / 256, 256>>>(pool);
    update_kernel<<<NB, 256>>>(pri, counts);
    cudaEventRecord(evUPD, 0);
    // export on side stream (depends only on pool/pri/counts)
    constexpr int RET = NBT * ND;
    constexpr int REST = NB * NP * NS + NB * NP + NB;
    if (out_size >= RET + REST) {
        cudaStreamWaitEvent(s1, evUPD, 0);
        export_kernel<<<(REST + 255) / 256, 256, 0, s1>>>(out + (long long)RET);
    }
    // poolT = pool^T per batch
    transpose_kernel<<<dim3(NP / 32, NS / 32, NB), dim3(32, 8)>>>(ppool, ppoolT, NP, NS,
        (long long)NP * NS, (long long)NS * NP);
    // join qk chain, then attn = qk @ poolT
    cudaStreamWaitEvent(0, evQK, 0);
    sgemm128_kernel<<<dim3(NP / 128, NT / 128, NB), 256>>>(pq, ppoolT, pattn, NT, NP, NS,
        (long long)NT * NS, (long long)NS * NP, (long long)NT * NP);
    softmax_kernel<<<NBT / 8, 256>>>();
    // ap = attn @ pool ; retrieved = ap @ wv
    sgemm128_kernel<<<dim3(NS / 128, NT / 128, NB), 256>>>(pattn, ppool, pap, NT, NS, NP,
        (long long)NT * NP, (long long)NP * NS, (long long)NT * NS);
    sgemm128_kernel<<<dim3(ND / 128, NBT / 128, 1), 256>>>(pap, wv, out, NBT, ND, NS, 0, 0, 0);
    // join export before returning control (keeps stream-0 the terminal node)
    cudaEvent_t evEXP;
    cudaEventCreateWithFlags(&evEXP, cudaEventDisableTiming);
    cudaEventRecord(evEXP, s1);
    cudaStreamWaitEvent(0, evEXP, 0);
}